// round 1
// baseline (speedup 1.0000x reference)
#include <cuda_runtime.h>
#include <cstdint>

// ---------------- problem constants ----------------
#define M_TOK   100352          // 32 * 64 * 49 tokens (window-gathered order)
#define CDIM    256
#define NHEADS  8
#define HD      32
#define TWIN    49              // tokens per window
#define NWIN    2048            // 32 batches * 64 windows

// ---------------- GEMM tiling ----------------
#define BM 64
#define BN 64
#define BK 32
#define SSTRIDE 36              // smem row stride (pad): 16B aligned, conflict-free

// scratch: Q|K|V, each [M_TOK][CDIM], window-gathered row order
__device__ float g_qkv[3ull * M_TOK * CDIM];

__device__ __forceinline__ unsigned cvt_tf32(float x) {
    unsigned r;
    asm("cvt.rna.tf32.f32 %0, %1;" : "=r"(r) : "f"(x));
    return r;
}

__device__ __forceinline__ void mma_tf32(float c[4], const unsigned a[4], const unsigned b[2]) {
    asm volatile(
        "mma.sync.aligned.m16n8k8.row.col.f32.tf32.tf32.f32 "
        "{%0,%1,%2,%3}, {%4,%5,%6,%7}, {%8,%9}, {%0,%1,%2,%3};"
        : "+f"(c[0]), "+f"(c[1]), "+f"(c[2]), "+f"(c[3])
        : "r"(a[0]), "r"(a[1]), "r"(a[2]), "r"(a[3]), "r"(b[0]), "r"(b[1]));
}

// ================= Kernel 1: fused window-gather + QKV projection =================
// Computes Y = gather(x) @ W^T + b for Wq, Wk, Wv (N dim = 768 = 3*256).
// Output rows are in window-gathered order so kernel 2 reads contiguously.
__global__ void __launch_bounds__(128) qkv_proj_kernel(
    const float* __restrict__ x,
    const float* __restrict__ Wq, const float* __restrict__ bq,
    const float* __restrict__ Wk, const float* __restrict__ bk,
    const float* __restrict__ Wv, const float* __restrict__ bv)
{
    __shared__ float As[BM * SSTRIDE];
    __shared__ float Bs[BN * SSTRIDE];

    const int tid  = threadIdx.x;
    const int warp = tid >> 5;
    const int lane = tid & 31;
    const int g    = lane >> 2;     // group id (0..7)
    const int tig  = lane & 3;      // thread-in-group (0..3)
    const int wm   = warp >> 1;     // warp tile row (0..1)
    const int wn   = warp & 1;      // warp tile col (0..1)

    const int n_block = blockIdx.y * BN;      // 0..704 step 64
    const int proj    = n_block >> 8;         // 0=Q, 1=K, 2=V
    const int d_base  = n_block & 255;        // column base within the 256-wide proj
    const float* __restrict__ W    = (proj == 0) ? Wq : ((proj == 1) ? Wk : Wv);
    const float* __restrict__ bias = (proj == 0) ? bq : ((proj == 1) ? bk : bv);

    const int p_block = blockIdx.x * BM;      // destination (window-ordered) row base

    // ---- global load assignment: each thread loads 4 float4 per tile ----
    const int lr = tid >> 3;            // 0..15: row group within tile
    const int kc = (tid & 7) * 4;       // col offset within BK

    long a_src[4];
    long b_src[4];
    #pragma unroll
    for (int i = 0; i < 4; i++) {
        // destination row p -> source row in x (window partition inverse)
        int p  = p_block + lr + 16 * i;
        int b  = p / 3136;              // 64*49
        int r  = p - b * 3136;
        int w  = r / 49;
        int t  = r - w * 49;
        int wy = w >> 3, wx = w & 7;
        int ty = t / 7,  tx = t - ty * 7;
        int src_row = (b * 56 + wy * 7 + ty) * 56 + wx * 7 + tx;
        a_src[i] = (long)src_row * CDIM;
        b_src[i] = (long)(d_base + lr + 16 * i) * CDIM;
    }

    float acc[2][4][4] = {};

    for (int k0 = 0; k0 < CDIM; k0 += BK) {
        #pragma unroll
        for (int i = 0; i < 4; i++) {
            float4 va = *(const float4*)(x + a_src[i] + k0 + kc);
            *(float4*)&As[(lr + 16 * i) * SSTRIDE + kc] = va;
            float4 vb = *(const float4*)(W + b_src[i] + k0 + kc);
            *(float4*)&Bs[(lr + 16 * i) * SSTRIDE + kc] = vb;
        }
        __syncthreads();

        #pragma unroll
        for (int ks = 0; ks < 4; ks++) {
            const int kk = ks * 8;
            unsigned afrag[2][4];
            unsigned bfrag[4][2];
            #pragma unroll
            for (int mi = 0; mi < 2; mi++) {
                int row = wm * 32 + mi * 16 + g;
                afrag[mi][0] = cvt_tf32(As[row * SSTRIDE + kk + tig]);
                afrag[mi][1] = cvt_tf32(As[(row + 8) * SSTRIDE + kk + tig]);
                afrag[mi][2] = cvt_tf32(As[row * SSTRIDE + kk + tig + 4]);
                afrag[mi][3] = cvt_tf32(As[(row + 8) * SSTRIDE + kk + tig + 4]);
            }
            #pragma unroll
            for (int ni = 0; ni < 4; ni++) {
                int nrow = wn * 32 + ni * 8 + g;
                bfrag[ni][0] = cvt_tf32(Bs[nrow * SSTRIDE + kk + tig]);
                bfrag[ni][1] = cvt_tf32(Bs[nrow * SSTRIDE + kk + tig + 4]);
            }
            #pragma unroll
            for (int mi = 0; mi < 2; mi++)
                #pragma unroll
                for (int ni = 0; ni < 4; ni++)
                    mma_tf32(acc[mi][ni], afrag[mi], bfrag[ni]);
        }
        __syncthreads();
    }

    // ---- epilogue: bias add + store into g_qkv (window-gathered rows) ----
    const size_t proj_off = (size_t)proj * M_TOK * CDIM;
    #pragma unroll
    for (int mi = 0; mi < 2; mi++) {
        int p0 = p_block + wm * 32 + mi * 16 + g;
        #pragma unroll
        for (int ni = 0; ni < 4; ni++) {
            int d = d_base + wn * 32 + ni * 8 + tig * 2;
            float b0v = bias[d];
            float b1v = bias[d + 1];
            float2 s0 = make_float2(acc[mi][ni][0] + b0v, acc[mi][ni][1] + b1v);
            float2 s1 = make_float2(acc[mi][ni][2] + b0v, acc[mi][ni][3] + b1v);
            *(float2*)&g_qkv[proj_off + (size_t)p0 * CDIM + d]       = s0;
            *(float2*)&g_qkv[proj_off + (size_t)(p0 + 8) * CDIM + d] = s1;
        }
    }
}

// ================= Kernel 2: per-(window, head) attention =================
__global__ void __launch_bounds__(256) attn_kernel(float* __restrict__ out)
{
    __shared__ float qs[TWIN * 33];
    __shared__ float ks[TWIN * 33];
    __shared__ float vs[TWIN * 33];
    __shared__ float lg[TWIN * TWIN];

    const int w   = blockIdx.x;   // 0..2047 (b*64 + window)
    const int h   = blockIdx.y;   // 0..7
    const int tid = threadIdx.x;

    const size_t base = (size_t)w * TWIN * CDIM + (size_t)h * HD;

    // load q, k, v tiles [49 x 32]
    for (int idx = tid; idx < 3 * TWIN * 8; idx += 256) {
        int mat = idx / (TWIN * 8);
        int rem = idx - mat * (TWIN * 8);
        int t   = rem >> 3;
        int c   = (rem & 7) * 4;
        float4 v = *(const float4*)(g_qkv + (size_t)mat * M_TOK * CDIM + base + (size_t)t * CDIM + c);
        float* dst = (mat == 0) ? qs : ((mat == 1) ? ks : vs);
        dst[t * 33 + c + 0] = v.x;
        dst[t * 33 + c + 1] = v.y;
        dst[t * 33 + c + 2] = v.z;
        dst[t * 33 + c + 3] = v.w;
    }
    __syncthreads();

    // logits[i][j] = (q_i . k_j) / sqrt(256)
    for (int idx = tid; idx < TWIN * TWIN; idx += 256) {
        int i = idx / TWIN;
        int j = idx - i * TWIN;
        float s = 0.f;
        #pragma unroll
        for (int c = 0; c < HD; c++)
            s += qs[i * 33 + c] * ks[j * 33 + c];
        lg[idx] = s * 0.0625f;
    }
    __syncthreads();

    // softmax per row: one warp per row
    const int warp = tid >> 5;
    const int lane = tid & 31;
    for (int r = warp; r < TWIN; r += 8) {
        bool has2 = (lane + 32) < TWIN;   // lanes 0..16 cover a second element
        float v0 = lg[r * TWIN + lane];
        float v1 = has2 ? lg[r * TWIN + lane + 32] : -1e30f;
        float m = fmaxf(v0, v1);
        #pragma unroll
        for (int off = 16; off > 0; off >>= 1)
            m = fmaxf(m, __shfl_xor_sync(0xffffffffu, m, off));
        float e0 = __expf(v0 - m);
        float e1 = has2 ? __expf(v1 - m) : 0.f;
        float s = e0 + e1;
        #pragma unroll
        for (int off = 16; off > 0; off >>= 1)
            s += __shfl_xor_sync(0xffffffffu, s, off);
        float inv = 1.f / s;
        lg[r * TWIN + lane] = e0 * inv;
        if (has2) lg[r * TWIN + lane + 32] = e1 * inv;
    }
    __syncthreads();

    // out[i][d] = sum_j attn[i][j] * v[j][d]
    for (int idx = tid; idx < TWIN * HD; idx += 256) {
        int i = idx >> 5;
        int d = idx & 31;
        float s = 0.f;
        #pragma unroll 7
        for (int j = 0; j < TWIN; j++)
            s += lg[i * TWIN + j] * vs[j * 33 + d];
        out[((size_t)w * TWIN + i) * CDIM + (size_t)h * HD + d] = s;
    }
}

// ================= launch =================
extern "C" void kernel_launch(void* const* d_in, const int* in_sizes, int n_in,
                              void* d_out, int out_size) {
    const float* x  = (const float*)d_in[0];
    const float* Wq = (const float*)d_in[1];
    const float* bq = (const float*)d_in[2];
    const float* Wk = (const float*)d_in[3];
    const float* bk = (const float*)d_in[4];
    const float* Wv = (const float*)d_in[5];
    const float* bv = (const float*)d_in[6];
    float* out = (float*)d_out;

    dim3 g1(M_TOK / BM, (3 * CDIM) / BN);   // 1568 x 12
    qkv_proj_kernel<<<g1, 128>>>(x, Wq, bq, Wk, bk, Wv, bv);

    dim3 g2(NWIN, NHEADS);                  // 2048 x 8
    attn_kernel<<<g2, 256>>>(out);
}

// round 3
// speedup vs baseline: 1.5369x; 1.5369x over previous
#include <cuda_runtime.h>
#include <cstdint>

// ---------------- problem constants ----------------
#define M_TOK   100352          // 32 * 64 * 49 tokens (window-gathered order)
#define CDIM    256
#define NHEADS  8
#define HD      32
#define TWIN    49              // tokens per window
#define NWIN    2048            // 32 batches * 64 windows

// ---------------- GEMM tiling ----------------
#define BM 64
#define BN 64
#define BK 32
#define SSTRIDE 36              // smem row stride (pad): 16B aligned, conflict-free

// scratch: Q|K|V, each [M_TOK][CDIM], window-gathered row order
__device__ float g_qkv[3ull * M_TOK * CDIM];

__device__ __forceinline__ unsigned cvt_tf32(float x) {
    unsigned r;
    asm("cvt.rna.tf32.f32 %0, %1;" : "=r"(r) : "f"(x));
    return r;
}

__device__ __forceinline__ float4 cvt4_tf32(float4 v) {
    float4 r;
    r.x = __uint_as_float(cvt_tf32(v.x));
    r.y = __uint_as_float(cvt_tf32(v.y));
    r.z = __uint_as_float(cvt_tf32(v.z));
    r.w = __uint_as_float(cvt_tf32(v.w));
    return r;
}

__device__ __forceinline__ void mma_tf32(float c[4], const unsigned a[4], const unsigned b[2]) {
    asm volatile(
        "mma.sync.aligned.m16n8k8.row.col.f32.tf32.tf32.f32 "
        "{%0,%1,%2,%3}, {%4,%5,%6,%7}, {%8,%9}, {%0,%1,%2,%3};"
        : "+f"(c[0]), "+f"(c[1]), "+f"(c[2]), "+f"(c[3])
        : "r"(a[0]), "r"(a[1]), "r"(a[2]), "r"(a[3]), "r"(b[0]), "r"(b[1]));
}

// ================= Kernel 1: fused window-gather + QKV projection =================
// Double-buffered smem, tf32 conversion once at smem-store time.
__global__ void __launch_bounds__(128) qkv_proj_kernel(
    const float* __restrict__ x,
    const float* __restrict__ Wq, const float* __restrict__ bq,
    const float* __restrict__ Wk, const float* __restrict__ bk,
    const float* __restrict__ Wv, const float* __restrict__ bv)
{
    __shared__ __align__(16) float As[2][BM * SSTRIDE];
    __shared__ __align__(16) float Bs[2][BM * SSTRIDE];

    const int tid  = threadIdx.x;
    const int warp = tid >> 5;
    const int lane = tid & 31;
    const int g    = lane >> 2;     // group id (0..7)
    const int tig  = lane & 3;      // thread-in-group (0..3)
    const int wm   = warp >> 1;     // warp tile row (0..1)
    const int wn   = warp & 1;      // warp tile col (0..1)

    const int n_block = blockIdx.y * BN;      // 0..704 step 64
    const int proj    = n_block >> 8;         // 0=Q, 1=K, 2=V
    const int d_base  = n_block & 255;        // column base within the 256-wide proj
    const float* __restrict__ W    = (proj == 0) ? Wq : ((proj == 1) ? Wk : Wv);
    const float* __restrict__ bias = (proj == 0) ? bq : ((proj == 1) ? bk : bv);

    const int p_block = blockIdx.x * BM;      // destination (window-ordered) row base

    // ---- global load assignment: each thread loads 4 float4 per tile ----
    const int lr = tid >> 3;            // 0..15: row group within tile
    const int kc = (tid & 7) * 4;       // col offset within BK

    long a_src[4];
    long b_src[4];
    #pragma unroll
    for (int i = 0; i < 4; i++) {
        // destination row p -> source row in x (window partition inverse)
        int p  = p_block + lr + 16 * i;
        int b  = p / 3136;              // 64*49
        int r  = p - b * 3136;
        int w  = r / 49;
        int t  = r - w * 49;
        int wy = w >> 3, wx = w & 7;
        int ty = t / 7,  tx = t - ty * 7;
        int src_row = (b * 56 + wy * 7 + ty) * 56 + wx * 7 + tx;
        a_src[i] = (long)src_row * CDIM;
        b_src[i] = (long)(d_base + lr + 16 * i) * CDIM;
    }

    float4 va[4], vb[4];
    // prologue: load first k-tile
    #pragma unroll
    for (int i = 0; i < 4; i++) {
        va[i] = *(const float4*)(x + a_src[i] + kc);
        vb[i] = *(const float4*)(W + b_src[i] + kc);
    }
    #pragma unroll
    for (int i = 0; i < 4; i++) {
        *(float4*)&As[0][(lr + 16 * i) * SSTRIDE + kc] = cvt4_tf32(va[i]);
        *(float4*)&Bs[0][(lr + 16 * i) * SSTRIDE + kc] = cvt4_tf32(vb[i]);
    }
    __syncthreads();

    float acc[2][4][4] = {};
    int buf = 0;

    for (int k0 = 0; k0 < CDIM; k0 += BK) {
        const bool last = (k0 + BK >= CDIM);
        if (!last) {
            #pragma unroll
            for (int i = 0; i < 4; i++) {
                va[i] = *(const float4*)(x + a_src[i] + k0 + BK + kc);
                vb[i] = *(const float4*)(W + b_src[i] + k0 + BK + kc);
            }
        }

        #pragma unroll
        for (int ks = 0; ks < 4; ks++) {
            const int kk = ks * 8;
            unsigned afrag[2][4];
            unsigned bfrag[4][2];
            #pragma unroll
            for (int mi = 0; mi < 2; mi++) {
                int row = wm * 32 + mi * 16 + g;
                afrag[mi][0] = __float_as_uint(As[buf][row * SSTRIDE + kk + tig]);
                afrag[mi][1] = __float_as_uint(As[buf][(row + 8) * SSTRIDE + kk + tig]);
                afrag[mi][2] = __float_as_uint(As[buf][row * SSTRIDE + kk + tig + 4]);
                afrag[mi][3] = __float_as_uint(As[buf][(row + 8) * SSTRIDE + kk + tig + 4]);
            }
            #pragma unroll
            for (int ni = 0; ni < 4; ni++) {
                int nrow = wn * 32 + ni * 8 + g;
                bfrag[ni][0] = __float_as_uint(Bs[buf][nrow * SSTRIDE + kk + tig]);
                bfrag[ni][1] = __float_as_uint(Bs[buf][nrow * SSTRIDE + kk + tig + 4]);
            }
            #pragma unroll
            for (int mi = 0; mi < 2; mi++)
                #pragma unroll
                for (int ni = 0; ni < 4; ni++)
                    mma_tf32(acc[mi][ni], afrag[mi], bfrag[ni]);
        }

        if (!last) {
            #pragma unroll
            for (int i = 0; i < 4; i++) {
                *(float4*)&As[buf ^ 1][(lr + 16 * i) * SSTRIDE + kc] = cvt4_tf32(va[i]);
                *(float4*)&Bs[buf ^ 1][(lr + 16 * i) * SSTRIDE + kc] = cvt4_tf32(vb[i]);
            }
            __syncthreads();
        }
        buf ^= 1;
    }

    // ---- epilogue: bias add + store into g_qkv (window-gathered rows) ----
    const size_t proj_off = (size_t)proj * M_TOK * CDIM;
    #pragma unroll
    for (int mi = 0; mi < 2; mi++) {
        int p0 = p_block + wm * 32 + mi * 16 + g;
        #pragma unroll
        for (int ni = 0; ni < 4; ni++) {
            int d = d_base + wn * 32 + ni * 8 + tig * 2;
            float b0v = bias[d];
            float b1v = bias[d + 1];
            float2 s0 = make_float2(acc[mi][ni][0] + b0v, acc[mi][ni][1] + b1v);
            float2 s1 = make_float2(acc[mi][ni][2] + b0v, acc[mi][ni][3] + b1v);
            *(float2*)&g_qkv[proj_off + (size_t)p0 * CDIM + d]       = s0;
            *(float2*)&g_qkv[proj_off + (size_t)(p0 + 8) * CDIM + d] = s1;
        }
    }
}

// ================= Kernel 2: per-(window, head) attention, register-tiled =================
#define QS_STRIDE 33
#define VS_STRIDE 32

__global__ void __launch_bounds__(128) attn_kernel(float* __restrict__ out)
{
    __shared__ __align__(16) float qs[52 * QS_STRIDE];  // padded to 52 rows (rows 49..51 zero)
    __shared__ __align__(16) float ks[TWIN * QS_STRIDE];
    __shared__ __align__(16) float vs[TWIN * VS_STRIDE];
    __shared__ __align__(16) float lg[52 * TWIN];       // rows 49..51 scratch (never stored out)

    const int w   = blockIdx.x;   // 0..2047 (b*64 + window)
    const int h   = blockIdx.y;   // 0..7
    const int tid = threadIdx.x;  // 128 threads

    const size_t base = (size_t)w * TWIN * CDIM + (size_t)h * HD;

    // zero q pad rows (rows 49..51)
    for (int i = tid; i < 3 * QS_STRIDE; i += 128)
        qs[49 * QS_STRIDE + i] = 0.f;

    // load q, k, v tiles [49 x 32]
    for (int idx = tid; idx < 3 * TWIN * 8; idx += 128) {
        int mat = idx / (TWIN * 8);
        int rem = idx - mat * (TWIN * 8);
        int t   = rem >> 3;
        int c   = (rem & 7) * 4;
        float4 v = *(const float4*)(g_qkv + (size_t)mat * M_TOK * CDIM + base + (size_t)t * CDIM + c);
        if (mat == 2) {
            *(float4*)&vs[t * VS_STRIDE + c] = v;
        } else {
            float* dst = (mat == 0) ? qs : ks;
            dst[t * QS_STRIDE + c + 0] = v.x;
            dst[t * QS_STRIDE + c + 1] = v.y;
            dst[t * QS_STRIDE + c + 2] = v.z;
            dst[t * QS_STRIDE + c + 3] = v.w;
        }
    }
    __syncthreads();

    // ---- logits: per-thread 4(i) x 7(j) register tile. 13 * 7 = 91 active threads ----
    if (tid < 91) {
        const int ti = tid / 7;
        const int tj = tid - ti * 7;
        const int i0 = ti * 4;      // 0..48
        const int j0 = tj * 7;      // 0..42 (covers j 0..48 exactly)
        float acc[4][7] = {};
        #pragma unroll 8
        for (int c = 0; c < HD; c++) {
            float qv[4], kv[7];
            #pragma unroll
            for (int r = 0; r < 4; r++) qv[r] = qs[(i0 + r) * QS_STRIDE + c];
            #pragma unroll
            for (int s = 0; s < 7; s++) kv[s] = ks[(j0 + s) * QS_STRIDE + c];
            #pragma unroll
            for (int r = 0; r < 4; r++)
                #pragma unroll
                for (int s = 0; s < 7; s++)
                    acc[r][s] = fmaf(qv[r], kv[s], acc[r][s]);
        }
        #pragma unroll
        for (int r = 0; r < 4; r++) {
            if (i0 + r < TWIN) {
                #pragma unroll
                for (int s = 0; s < 7; s++)
                    lg[(i0 + r) * TWIN + j0 + s] = acc[r][s] * 0.0625f;
            }
        }
    }
    __syncthreads();

    // ---- softmax per row: one warp per row, 4 warps ----
    const int warp = tid >> 5;
    const int lane = tid & 31;
    for (int r = warp; r < TWIN; r += 4) {
        bool has2 = (lane + 32) < TWIN;
        float v0 = lg[r * TWIN + lane];
        float v1 = has2 ? lg[r * TWIN + lane + 32] : -1e30f;
        float m = fmaxf(v0, v1);
        #pragma unroll
        for (int off = 16; off > 0; off >>= 1)
            m = fmaxf(m, __shfl_xor_sync(0xffffffffu, m, off));
        float e0 = __expf(v0 - m);
        float e1 = has2 ? __expf(v1 - m) : 0.f;
        float s = e0 + e1;
        #pragma unroll
        for (int off = 16; off > 0; off >>= 1)
            s += __shfl_xor_sync(0xffffffffu, s, off);
        float inv = 1.f / s;
        lg[r * TWIN + lane] = e0 * inv;
        if (has2) lg[r * TWIN + lane + 32] = e1 * inv;
    }
    __syncthreads();

    // ---- PV: per-thread 4(i) x 4(d) register tile. 13 * 8 = 104 active threads ----
    if (tid < 104) {
        const int ti = tid >> 3;
        const int td = tid & 7;
        const int i0 = ti * 4;      // 0..48
        const int d0 = td * 4;      // 0..28
        float acc[4][4] = {};
        #pragma unroll 7
        for (int j = 0; j < TWIN; j++) {
            float a[4];
            #pragma unroll
            for (int r = 0; r < 4; r++) a[r] = lg[(i0 + r) * TWIN + j];
            float4 b = *(const float4*)&vs[j * VS_STRIDE + d0];
            #pragma unroll
            for (int r = 0; r < 4; r++) {
                acc[r][0] = fmaf(a[r], b.x, acc[r][0]);
                acc[r][1] = fmaf(a[r], b.y, acc[r][1]);
                acc[r][2] = fmaf(a[r], b.z, acc[r][2]);
                acc[r][3] = fmaf(a[r], b.w, acc[r][3]);
            }
        }
        #pragma unroll
        for (int r = 0; r < 4; r++) {
            int i = i0 + r;
            if (i < TWIN) {
                float4 o = make_float4(acc[r][0], acc[r][1], acc[r][2], acc[r][3]);
                *(float4*)&out[((size_t)w * TWIN + i) * CDIM + (size_t)h * HD + d0] = o;
            }
        }
    }
}

// ================= launch =================
extern "C" void kernel_launch(void* const* d_in, const int* in_sizes, int n_in,
                              void* d_out, int out_size) {
    const float* x  = (const float*)d_in[0];
    const float* Wq = (const float*)d_in[1];
    const float* bq = (const float*)d_in[2];
    const float* Wk = (const float*)d_in[3];
    const float* bk = (const float*)d_in[4];
    const float* Wv = (const float*)d_in[5];
    const float* bv = (const float*)d_in[6];
    float* out = (float*)d_out;

    dim3 g1(M_TOK / BM, (3 * CDIM) / BN);   // 1568 x 12
    qkv_proj_kernel<<<g1, 128>>>(x, Wq, bq, Wk, bk, Wv, bv);

    dim3 g2(NWIN, NHEADS);                  // 2048 x 8
    attn_kernel<<<g2, 128>>>(out);
}

// round 4
// speedup vs baseline: 1.7439x; 1.1347x over previous
#include <cuda_runtime.h>
#include <cstdint>

// ---------------- problem constants ----------------
#define M_TOK   100352          // 32 * 64 * 49 tokens (window-gathered order)
#define CDIM    256
#define NHEADS  8
#define HD      32
#define TWIN    49              // tokens per window
#define NWIN    2048            // 32 batches * 64 windows

// ---------------- GEMM tiling (proj v2) ----------------
#define BM 64                   // rows per CTA (x tile, K=256 fully resident)
#define BN2 128                 // output cols per n-iter
#define NITER 6                 // 768 / 128
#define BK 32                   // k-chunk for W streaming
#define A_STRIDE 260            // smem row stride for As (256 + 4)
#define B_STRIDE 36             // smem row stride for Bs (32 + 4)
#define SMEM_PROJ_BYTES ((64 * A_STRIDE + 2 * BN2 * B_STRIDE) * 4)   // 103424

// scratch: Q|K|V, each [M_TOK][CDIM], window-gathered row order
__device__ float g_qkv[3ull * M_TOK * CDIM];

__device__ __forceinline__ unsigned cvt_tf32(float x) {
    unsigned r;
    asm("cvt.rna.tf32.f32 %0, %1;" : "=r"(r) : "f"(x));
    return r;
}

__device__ __forceinline__ float4 cvt4_tf32(float4 v) {
    float4 r;
    r.x = __uint_as_float(cvt_tf32(v.x));
    r.y = __uint_as_float(cvt_tf32(v.y));
    r.z = __uint_as_float(cvt_tf32(v.z));
    r.w = __uint_as_float(cvt_tf32(v.w));
    return r;
}

__device__ __forceinline__ void mma_tf32(float c[4], const unsigned a[4], const unsigned b[2]) {
    asm volatile(
        "mma.sync.aligned.m16n8k8.row.col.f32.tf32.tf32.f32 "
        "{%0,%1,%2,%3}, {%4,%5,%6,%7}, {%8,%9}, {%0,%1,%2,%3};"
        : "+f"(c[0]), "+f"(c[1]), "+f"(c[2]), "+f"(c[3])
        : "r"(a[0]), "r"(a[1]), "r"(a[2]), "r"(a[3]), "r"(b[0]), "r"(b[1]));
}

// ================= Kernel 1: fused window-gather + QKV projection (v2) =================
// x tile (64 rows x 256 K) resident in smem across the whole N=768 loop.
// W streamed through double-buffered smem (L2-hot: 768 KB total).
__global__ void __launch_bounds__(256) qkv_proj_kernel(
    const float* __restrict__ x,
    const float* __restrict__ Wq, const float* __restrict__ bq,
    const float* __restrict__ Wk, const float* __restrict__ bk,
    const float* __restrict__ Wv, const float* __restrict__ bv)
{
    extern __shared__ float sm[];
    float* As  = sm;                        // 64 x A_STRIDE
    float* Bs0 = sm + 64 * A_STRIDE;        // 2 x (BN2 x B_STRIDE)

    const int tid  = threadIdx.x;
    const int warp = tid >> 5;
    const int lane = tid & 31;
    const int g    = lane >> 2;     // 0..7
    const int tig  = lane & 3;      // 0..3
    const int wm   = warp >> 2;     // 0..1 (32-row warp tile)
    const int wn   = warp & 3;      // 0..3 (32-col warp tile)

    const int p_block = blockIdx.x * BM;    // destination (window-ordered) row base

    // ---- load A tile: 64 rows x 256 cols, gathered, cvt to tf32 once ----
    {
        const int arow = tid >> 2;          // 0..63
        const int aq   = tid & 3;           // quad group
        int p  = p_block + arow;
        int b  = p / 3136;                  // 64*49
        int r  = p - b * 3136;
        int w  = r / 49;
        int t  = r - w * 49;
        int wy = w >> 3, wx = w & 7;
        int ty = t / 7,  tx = t - ty * 7;
        const float* asrc = x + (long)((b * 56 + wy * 7 + ty) * 56 + wx * 7 + tx) * CDIM;
        #pragma unroll
        for (int j = 0; j < 16; j++) {
            int c = (aq + 4 * j) * 4;
            float4 v = *(const float4*)(asrc + c);
            *(float4*)&As[arow * A_STRIDE + c] = cvt4_tf32(v);
        }
    }

    // ---- B loader assignment: 128 rows x 8 quads per k-chunk, 4 float4/thread ----
    const int lr = tid >> 3;                // 0..31
    const int kc = (tid & 7) * 4;           // col offset within BK

    float4 vb[4];

    for (int n = 0; n < NITER; n++) {
        const int proj = n >> 1;            // 0=Q,1=K,2=V
        const int dloc = (n & 1) * BN2;     // 0 or 128 within the 256-wide proj
        const float* __restrict__ W    = (proj == 0) ? Wq : ((proj == 1) ? Wk : Wv);
        const float* __restrict__ bias = (proj == 0) ? bq : ((proj == 1) ? bk : bv);

        // prologue: load first k-chunk of this n-iter
        #pragma unroll
        for (int i = 0; i < 4; i++)
            vb[i] = *(const float4*)(W + (long)(dloc + lr + 32 * i) * CDIM + kc);

        __syncthreads();   // previous n-iter compute done (also covers A-load on n=0)
        #pragma unroll
        for (int i = 0; i < 4; i++)
            *(float4*)&Bs0[(lr + 32 * i) * B_STRIDE + kc] = cvt4_tf32(vb[i]);
        __syncthreads();

        float acc[2][4][4] = {};
        int buf = 0;

        for (int kt = 0; kt < 8; kt++) {
            if (kt < 7) {
                #pragma unroll
                for (int i = 0; i < 4; i++)
                    vb[i] = *(const float4*)(W + (long)(dloc + lr + 32 * i) * CDIM + (kt + 1) * BK + kc);
            }

            const float* Bsb = Bs0 + buf * (BN2 * B_STRIDE);
            #pragma unroll
            for (int ks = 0; ks < 4; ks++) {
                const int kk = kt * 32 + ks * 8;   // col in As
                const int kb = ks * 8;             // col in Bs
                unsigned afrag[2][4];
                unsigned bfrag[4][2];
                #pragma unroll
                for (int mi = 0; mi < 2; mi++) {
                    int row = wm * 32 + mi * 16 + g;
                    afrag[mi][0] = __float_as_uint(As[row * A_STRIDE + kk + tig]);
                    afrag[mi][1] = __float_as_uint(As[(row + 8) * A_STRIDE + kk + tig]);
                    afrag[mi][2] = __float_as_uint(As[row * A_STRIDE + kk + tig + 4]);
                    afrag[mi][3] = __float_as_uint(As[(row + 8) * A_STRIDE + kk + tig + 4]);
                }
                #pragma unroll
                for (int ni = 0; ni < 4; ni++) {
                    int nrow = wn * 32 + ni * 8 + g;
                    bfrag[ni][0] = __float_as_uint(Bsb[nrow * B_STRIDE + kb + tig]);
                    bfrag[ni][1] = __float_as_uint(Bsb[nrow * B_STRIDE + kb + tig + 4]);
                }
                #pragma unroll
                for (int mi = 0; mi < 2; mi++)
                    #pragma unroll
                    for (int ni = 0; ni < 4; ni++)
                        mma_tf32(acc[mi][ni], afrag[mi], bfrag[ni]);
            }

            if (kt < 7) {
                float* Bn = Bs0 + (buf ^ 1) * (BN2 * B_STRIDE);
                #pragma unroll
                for (int i = 0; i < 4; i++)
                    *(float4*)&Bn[(lr + 32 * i) * B_STRIDE + kc] = cvt4_tf32(vb[i]);
                __syncthreads();
            }
            buf ^= 1;
        }

        // ---- epilogue for this n-iter: bias add + store ----
        const size_t proj_off = (size_t)proj * M_TOK * CDIM;
        #pragma unroll
        for (int mi = 0; mi < 2; mi++) {
            int p0 = p_block + wm * 32 + mi * 16 + g;
            #pragma unroll
            for (int ni = 0; ni < 4; ni++) {
                int d = dloc + wn * 32 + ni * 8 + tig * 2;
                float b0v = bias[d];
                float b1v = bias[d + 1];
                float2 s0 = make_float2(acc[mi][ni][0] + b0v, acc[mi][ni][1] + b1v);
                float2 s1 = make_float2(acc[mi][ni][2] + b0v, acc[mi][ni][3] + b1v);
                *(float2*)&g_qkv[proj_off + (size_t)p0 * CDIM + d]       = s0;
                *(float2*)&g_qkv[proj_off + (size_t)(p0 + 8) * CDIM + d] = s1;
            }
        }
    }
}

// ================= Kernel 2: per-(window, head) attention, register-tiled =================
#define QS_STRIDE 33
#define VS_STRIDE 32

__global__ void __launch_bounds__(128) attn_kernel(float* __restrict__ out)
{
    __shared__ __align__(16) float qs[52 * QS_STRIDE];  // padded to 52 rows (rows 49..51 zero)
    __shared__ __align__(16) float ks[TWIN * QS_STRIDE];
    __shared__ __align__(16) float vs[TWIN * VS_STRIDE];
    __shared__ __align__(16) float lg[52 * TWIN];       // rows 49..51 scratch (never stored out)

    const int w   = blockIdx.x;   // 0..2047 (b*64 + window)
    const int h   = blockIdx.y;   // 0..7
    const int tid = threadIdx.x;  // 128 threads

    const size_t base = (size_t)w * TWIN * CDIM + (size_t)h * HD;

    // zero q pad rows (rows 49..51)
    for (int i = tid; i < 3 * QS_STRIDE; i += 128)
        qs[49 * QS_STRIDE + i] = 0.f;

    // load q, k, v tiles [49 x 32]
    for (int idx = tid; idx < 3 * TWIN * 8; idx += 128) {
        int mat = idx / (TWIN * 8);
        int rem = idx - mat * (TWIN * 8);
        int t   = rem >> 3;
        int c   = (rem & 7) * 4;
        float4 v = *(const float4*)(g_qkv + (size_t)mat * M_TOK * CDIM + base + (size_t)t * CDIM + c);
        if (mat == 2) {
            *(float4*)&vs[t * VS_STRIDE + c] = v;
        } else {
            float* dst = (mat == 0) ? qs : ks;
            dst[t * QS_STRIDE + c + 0] = v.x;
            dst[t * QS_STRIDE + c + 1] = v.y;
            dst[t * QS_STRIDE + c + 2] = v.z;
            dst[t * QS_STRIDE + c + 3] = v.w;
        }
    }
    __syncthreads();

    // ---- logits: per-thread 4(i) x 7(j) register tile. 13 * 7 = 91 active threads ----
    if (tid < 91) {
        const int ti = tid / 7;
        const int tj = tid - ti * 7;
        const int i0 = ti * 4;      // 0..48
        const int j0 = tj * 7;      // 0..42 (covers j 0..48 exactly)
        float acc[4][7] = {};
        #pragma unroll 8
        for (int c = 0; c < HD; c++) {
            float qv[4], kv[7];
            #pragma unroll
            for (int r = 0; r < 4; r++) qv[r] = qs[(i0 + r) * QS_STRIDE + c];
            #pragma unroll
            for (int s = 0; s < 7; s++) kv[s] = ks[(j0 + s) * QS_STRIDE + c];
            #pragma unroll
            for (int r = 0; r < 4; r++)
                #pragma unroll
                for (int s = 0; s < 7; s++)
                    acc[r][s] = fmaf(qv[r], kv[s], acc[r][s]);
        }
        #pragma unroll
        for (int r = 0; r < 4; r++) {
            if (i0 + r < TWIN) {
                #pragma unroll
                for (int s = 0; s < 7; s++)
                    lg[(i0 + r) * TWIN + j0 + s] = acc[r][s] * 0.0625f;
            }
        }
    }
    __syncthreads();

    // ---- softmax per row: one warp per row, 4 warps ----
    const int warp = tid >> 5;
    const int lane = tid & 31;
    for (int r = warp; r < TWIN; r += 4) {
        bool has2 = (lane + 32) < TWIN;
        float v0 = lg[r * TWIN + lane];
        float v1 = has2 ? lg[r * TWIN + lane + 32] : -1e30f;
        float m = fmaxf(v0, v1);
        #pragma unroll
        for (int off = 16; off > 0; off >>= 1)
            m = fmaxf(m, __shfl_xor_sync(0xffffffffu, m, off));
        float e0 = __expf(v0 - m);
        float e1 = has2 ? __expf(v1 - m) : 0.f;
        float s = e0 + e1;
        #pragma unroll
        for (int off = 16; off > 0; off >>= 1)
            s += __shfl_xor_sync(0xffffffffu, s, off);
        float inv = 1.f / s;
        lg[r * TWIN + lane] = e0 * inv;
        if (has2) lg[r * TWIN + lane + 32] = e1 * inv;
    }
    __syncthreads();

    // ---- PV: per-thread 4(i) x 4(d) register tile. 13 * 8 = 104 active threads ----
    if (tid < 104) {
        const int ti = tid >> 3;
        const int td = tid & 7;
        const int i0 = ti * 4;      // 0..48
        const int d0 = td * 4;      // 0..28
        float acc[4][4] = {};
        #pragma unroll 7
        for (int j = 0; j < TWIN; j++) {
            float a[4];
            #pragma unroll
            for (int r = 0; r < 4; r++) a[r] = lg[(i0 + r) * TWIN + j];
            float4 b = *(const float4*)&vs[j * VS_STRIDE + d0];
            #pragma unroll
            for (int r = 0; r < 4; r++) {
                acc[r][0] = fmaf(a[r], b.x, acc[r][0]);
                acc[r][1] = fmaf(a[r], b.y, acc[r][1]);
                acc[r][2] = fmaf(a[r], b.z, acc[r][2]);
                acc[r][3] = fmaf(a[r], b.w, acc[r][3]);
            }
        }
        #pragma unroll
        for (int r = 0; r < 4; r++) {
            int i = i0 + r;
            if (i < TWIN) {
                float4 o = make_float4(acc[r][0], acc[r][1], acc[r][2], acc[r][3]);
                *(float4*)&out[((size_t)w * TWIN + i) * CDIM + (size_t)h * HD + d0] = o;
            }
        }
    }
}

// ================= launch =================
extern "C" void kernel_launch(void* const* d_in, const int* in_sizes, int n_in,
                              void* d_out, int out_size) {
    const float* x  = (const float*)d_in[0];
    const float* Wq = (const float*)d_in[1];
    const float* bq = (const float*)d_in[2];
    const float* Wk = (const float*)d_in[3];
    const float* bk = (const float*)d_in[4];
    const float* Wv = (const float*)d_in[5];
    const float* bv = (const float*)d_in[6];
    float* out = (float*)d_out;

    cudaFuncSetAttribute(qkv_proj_kernel,
                         cudaFuncAttributeMaxDynamicSharedMemorySize, SMEM_PROJ_BYTES);

    qkv_proj_kernel<<<M_TOK / BM, 256, SMEM_PROJ_BYTES>>>(x, Wq, bq, Wk, bk, Wv, bv);

    dim3 g2(NWIN, NHEADS);                  // 2048 x 8
    attn_kernel<<<g2, 128>>>(out);
}

// round 5
// speedup vs baseline: 2.1375x; 1.2257x over previous
#include <cuda_runtime.h>
#include <cstdint>

// ---------------- problem constants ----------------
#define M_TOK   100352          // 32 * 64 * 49 tokens (window-gathered order)
#define CDIM    256
#define NHEADS  8
#define HD      32
#define TWIN    49              // tokens per window
#define NWIN    2048            // 32 batches * 64 windows

// ---------------- GEMM tiling (proj v2) ----------------
#define BM 64                   // rows per CTA (x tile, K=256 fully resident)
#define BN2 128                 // output cols per n-iter
#define NITER 6                 // 768 / 128
#define BK 32                   // k-chunk for W streaming
#define A_STRIDE 260            // smem row stride for As (256 + 4)
#define B_STRIDE 36             // smem row stride for Bs (32 + 4)
#define SMEM_PROJ_BYTES ((64 * A_STRIDE + 2 * BN2 * B_STRIDE) * 4)   // 103424

// scratch: Q|K|V, each [M_TOK][CDIM], window-gathered row order
__device__ float g_qkv[3ull * M_TOK * CDIM];

__device__ __forceinline__ unsigned cvt_tf32(float x) {
    unsigned r;
    asm("cvt.rna.tf32.f32 %0, %1;" : "=r"(r) : "f"(x));
    return r;
}

__device__ __forceinline__ float4 cvt4_tf32(float4 v) {
    float4 r;
    r.x = __uint_as_float(cvt_tf32(v.x));
    r.y = __uint_as_float(cvt_tf32(v.y));
    r.z = __uint_as_float(cvt_tf32(v.z));
    r.w = __uint_as_float(cvt_tf32(v.w));
    return r;
}

__device__ __forceinline__ void mma_tf32(float c[4], const unsigned a[4], const unsigned b[2]) {
    asm volatile(
        "mma.sync.aligned.m16n8k8.row.col.f32.tf32.tf32.f32 "
        "{%0,%1,%2,%3}, {%4,%5,%6,%7}, {%8,%9}, {%0,%1,%2,%3};"
        : "+f"(c[0]), "+f"(c[1]), "+f"(c[2]), "+f"(c[3])
        : "r"(a[0]), "r"(a[1]), "r"(a[2]), "r"(a[3]), "r"(b[0]), "r"(b[1]));
}

// ================= Kernel 1: fused window-gather + QKV projection (v2) =================
__global__ void __launch_bounds__(256) qkv_proj_kernel(
    const float* __restrict__ x,
    const float* __restrict__ Wq, const float* __restrict__ bq,
    const float* __restrict__ Wk, const float* __restrict__ bk,
    const float* __restrict__ Wv, const float* __restrict__ bv)
{
    extern __shared__ float sm[];
    float* As  = sm;                        // 64 x A_STRIDE
    float* Bs0 = sm + 64 * A_STRIDE;        // 2 x (BN2 x B_STRIDE)

    const int tid  = threadIdx.x;
    const int warp = tid >> 5;
    const int lane = tid & 31;
    const int g    = lane >> 2;     // 0..7
    const int tig  = lane & 3;      // 0..3
    const int wm   = warp >> 2;     // 0..1 (32-row warp tile)
    const int wn   = warp & 3;      // 0..3 (32-col warp tile)

    const int p_block = blockIdx.x * BM;    // destination (window-ordered) row base

    // ---- load A tile: 64 rows x 256 cols, gathered, cvt to tf32 once ----
    {
        const int arow = tid >> 2;          // 0..63
        const int aq   = tid & 3;           // quad group
        int p  = p_block + arow;
        int b  = p / 3136;                  // 64*49
        int r  = p - b * 3136;
        int w  = r / 49;
        int t  = r - w * 49;
        int wy = w >> 3, wx = w & 7;
        int ty = t / 7,  tx = t - ty * 7;
        const float* asrc = x + (long)((b * 56 + wy * 7 + ty) * 56 + wx * 7 + tx) * CDIM;
        #pragma unroll
        for (int j = 0; j < 16; j++) {
            int c = (aq + 4 * j) * 4;
            float4 v = *(const float4*)(asrc + c);
            *(float4*)&As[arow * A_STRIDE + c] = cvt4_tf32(v);
        }
    }

    // ---- B loader assignment ----
    const int lr = tid >> 3;                // 0..31
    const int kc = (tid & 7) * 4;           // col offset within BK

    float4 vb[4];

    for (int n = 0; n < NITER; n++) {
        const int proj = n >> 1;            // 0=Q,1=K,2=V
        const int dloc = (n & 1) * BN2;     // 0 or 128 within the 256-wide proj
        const float* __restrict__ W    = (proj == 0) ? Wq : ((proj == 1) ? Wk : Wv);
        const float* __restrict__ bias = (proj == 0) ? bq : ((proj == 1) ? bk : bv);

        #pragma unroll
        for (int i = 0; i < 4; i++)
            vb[i] = *(const float4*)(W + (long)(dloc + lr + 32 * i) * CDIM + kc);

        __syncthreads();
        #pragma unroll
        for (int i = 0; i < 4; i++)
            *(float4*)&Bs0[(lr + 32 * i) * B_STRIDE + kc] = cvt4_tf32(vb[i]);
        __syncthreads();

        float acc[2][4][4] = {};
        int buf = 0;

        for (int kt = 0; kt < 8; kt++) {
            if (kt < 7) {
                #pragma unroll
                for (int i = 0; i < 4; i++)
                    vb[i] = *(const float4*)(W + (long)(dloc + lr + 32 * i) * CDIM + (kt + 1) * BK + kc);
            }

            const float* Bsb = Bs0 + buf * (BN2 * B_STRIDE);
            #pragma unroll
            for (int ks = 0; ks < 4; ks++) {
                const int kk = kt * 32 + ks * 8;   // col in As
                const int kb = ks * 8;             // col in Bs
                unsigned afrag[2][4];
                unsigned bfrag[4][2];
                #pragma unroll
                for (int mi = 0; mi < 2; mi++) {
                    int row = wm * 32 + mi * 16 + g;
                    afrag[mi][0] = __float_as_uint(As[row * A_STRIDE + kk + tig]);
                    afrag[mi][1] = __float_as_uint(As[(row + 8) * A_STRIDE + kk + tig]);
                    afrag[mi][2] = __float_as_uint(As[row * A_STRIDE + kk + tig + 4]);
                    afrag[mi][3] = __float_as_uint(As[(row + 8) * A_STRIDE + kk + tig + 4]);
                }
                #pragma unroll
                for (int ni = 0; ni < 4; ni++) {
                    int nrow = wn * 32 + ni * 8 + g;
                    bfrag[ni][0] = __float_as_uint(Bsb[nrow * B_STRIDE + kb + tig]);
                    bfrag[ni][1] = __float_as_uint(Bsb[nrow * B_STRIDE + kb + tig + 4]);
                }
                #pragma unroll
                for (int mi = 0; mi < 2; mi++)
                    #pragma unroll
                    for (int ni = 0; ni < 4; ni++)
                        mma_tf32(acc[mi][ni], afrag[mi], bfrag[ni]);
            }

            if (kt < 7) {
                float* Bn = Bs0 + (buf ^ 1) * (BN2 * B_STRIDE);
                #pragma unroll
                for (int i = 0; i < 4; i++)
                    *(float4*)&Bn[(lr + 32 * i) * B_STRIDE + kc] = cvt4_tf32(vb[i]);
                __syncthreads();
            }
            buf ^= 1;
        }

        const size_t proj_off = (size_t)proj * M_TOK * CDIM;
        #pragma unroll
        for (int mi = 0; mi < 2; mi++) {
            int p0 = p_block + wm * 32 + mi * 16 + g;
            #pragma unroll
            for (int ni = 0; ni < 4; ni++) {
                int d = dloc + wn * 32 + ni * 8 + tig * 2;
                float b0v = bias[d];
                float b1v = bias[d + 1];
                float2 s0 = make_float2(acc[mi][ni][0] + b0v, acc[mi][ni][1] + b1v);
                float2 s1 = make_float2(acc[mi][ni][2] + b0v, acc[mi][ni][3] + b1v);
                *(float2*)&g_qkv[proj_off + (size_t)p0 * CDIM + d]       = s0;
                *(float2*)&g_qkv[proj_off + (size_t)(p0 + 8) * CDIM + d] = s1;
            }
        }
    }
}

// ================= Kernel 2: tensor-core attention (tf32 mma) =================
// CTA = one (window, head). 4 warps, warp handles 16 query rows.
// QK^T and PV via m16n8k8 tf32 mma; softmax on accumulator fragments.
#define QK_ST 36                // qs/ks smem stride: frag bank = 4g+tig, conflict-free
#define V_ST  40                // vs smem stride: frag bank = 8tig+g, conflict-free

__global__ void __launch_bounds__(128) attn_kernel(float* __restrict__ out)
{
    __shared__ __align__(16) float qs[64 * QK_ST];   // rows 49..63 zero
    __shared__ __align__(16) float ks[56 * QK_ST];   // rows 49..55 zero
    __shared__ __align__(16) float vs[56 * V_ST];    // rows 49..55 zero (vital: P=0 x NaN)

    const int w   = blockIdx.x;   // 0..2047
    const int h   = blockIdx.y;   // 0..7
    const int tid = threadIdx.x;  // 128

    const size_t base = (size_t)w * TWIN * CDIM + (size_t)h * HD;

    // zero pad rows
    for (int i = tid; i < 15 * QK_ST; i += 128) qs[49 * QK_ST + i] = 0.f;
    for (int i = tid; i < 7 * QK_ST; i += 128)  ks[49 * QK_ST + i] = 0.f;
    for (int i = tid; i < 7 * V_ST; i += 128)   vs[49 * V_ST + i] = 0.f;

    // load q,k,v tiles [49 x 32], tf32-rounded at store
    for (int idx = tid; idx < 3 * TWIN * 8; idx += 128) {
        int mat = idx / (TWIN * 8);
        int rem = idx - mat * (TWIN * 8);
        int t   = rem >> 3;
        int c   = (rem & 7) * 4;
        float4 v = *(const float4*)(g_qkv + (size_t)mat * M_TOK * CDIM + base + (size_t)t * CDIM + c);
        v = cvt4_tf32(v);
        float* dst = (mat == 0) ? qs : ((mat == 1) ? ks : vs);
        int st = (mat == 2) ? V_ST : QK_ST;
        dst[t * st + c + 0] = v.x;
        dst[t * st + c + 1] = v.y;
        dst[t * st + c + 2] = v.z;
        dst[t * st + c + 3] = v.w;
    }
    __syncthreads();

    const int warp = tid >> 5;
    const int lane = tid & 31;
    const int g    = lane >> 2;   // 0..7
    const int tig  = lane & 3;    // 0..3
    const int i0   = warp * 16;   // query row base for this warp

    // ---- QK^T: acc[nt][0..3], nt = key-tile (8 cols each, 7 tiles = 56) ----
    float acc[7][4] = {};
    #pragma unroll
    for (int kt = 0; kt < 4; kt++) {
        const int c0 = kt * 8;
        unsigned a[4];
        a[0] = __float_as_uint(qs[(i0 + g) * QK_ST + c0 + tig]);
        a[1] = __float_as_uint(qs[(i0 + g + 8) * QK_ST + c0 + tig]);
        a[2] = __float_as_uint(qs[(i0 + g) * QK_ST + c0 + tig + 4]);
        a[3] = __float_as_uint(qs[(i0 + g + 8) * QK_ST + c0 + tig + 4]);
        #pragma unroll
        for (int nt = 0; nt < 7; nt++) {
            unsigned b[2];
            b[0] = __float_as_uint(ks[(nt * 8 + g) * QK_ST + c0 + tig]);
            b[1] = __float_as_uint(ks[(nt * 8 + g) * QK_ST + c0 + tig + 4]);
            mma_tf32(acc[nt], a, b);
        }
    }

    // ---- scale + mask padded key columns (j >= 49, all in tile 6) ----
    #pragma unroll
    for (int nt = 0; nt < 7; nt++) {
        acc[nt][0] *= 0.0625f; acc[nt][1] *= 0.0625f;
        acc[nt][2] *= 0.0625f; acc[nt][3] *= 0.0625f;
    }
    // tile6 cols: c0/c2 -> j=48+2*tig (valid only tig==0); c1/c3 -> j=49+2*tig (never)
    acc[6][1] = -1e30f; acc[6][3] = -1e30f;
    if (tig > 0) { acc[6][0] = -1e30f; acc[6][2] = -1e30f; }

    // ---- softmax on fragments: row g (regs 0,1) / row g+8 (regs 2,3) ----
    float m0 = -1e30f, m1 = -1e30f;
    #pragma unroll
    for (int nt = 0; nt < 7; nt++) {
        m0 = fmaxf(m0, fmaxf(acc[nt][0], acc[nt][1]));
        m1 = fmaxf(m1, fmaxf(acc[nt][2], acc[nt][3]));
    }
    m0 = fmaxf(m0, __shfl_xor_sync(0xffffffffu, m0, 1));
    m0 = fmaxf(m0, __shfl_xor_sync(0xffffffffu, m0, 2));
    m1 = fmaxf(m1, __shfl_xor_sync(0xffffffffu, m1, 1));
    m1 = fmaxf(m1, __shfl_xor_sync(0xffffffffu, m1, 2));

    float s0 = 0.f, s1 = 0.f;
    #pragma unroll
    for (int nt = 0; nt < 7; nt++) {
        acc[nt][0] = __expf(acc[nt][0] - m0);
        acc[nt][1] = __expf(acc[nt][1] - m0);
        acc[nt][2] = __expf(acc[nt][2] - m1);
        acc[nt][3] = __expf(acc[nt][3] - m1);
        s0 += acc[nt][0] + acc[nt][1];
        s1 += acc[nt][2] + acc[nt][3];
    }
    s0 += __shfl_xor_sync(0xffffffffu, s0, 1);
    s0 += __shfl_xor_sync(0xffffffffu, s0, 2);
    s1 += __shfl_xor_sync(0xffffffffu, s1, 1);
    s1 += __shfl_xor_sync(0xffffffffu, s1, 2);
    const float inv0 = 1.f / s0, inv1 = 1.f / s1;
    #pragma unroll
    for (int nt = 0; nt < 7; nt++) {
        acc[nt][0] *= inv0; acc[nt][1] *= inv0;
        acc[nt][2] *= inv1; acc[nt][3] *= inv1;
    }

    // ---- PV: P (C-fragment) -> A-fragment via quad shuffles, then mma ----
    float oacc[4][4] = {};
    const int srcA = (lane & ~3) | (tig >> 1);
    const int srcB = srcA + 2;
    const bool odd = tig & 1;

    #pragma unroll
    for (int kt = 0; kt < 7; kt++) {
        float x0 = __shfl_sync(0xffffffffu, acc[kt][0], srcA);
        float x1 = __shfl_sync(0xffffffffu, acc[kt][1], srcA);
        float x2 = __shfl_sync(0xffffffffu, acc[kt][2], srcA);
        float x3 = __shfl_sync(0xffffffffu, acc[kt][3], srcA);
        float y0 = __shfl_sync(0xffffffffu, acc[kt][0], srcB);
        float y1 = __shfl_sync(0xffffffffu, acc[kt][1], srcB);
        float y2 = __shfl_sync(0xffffffffu, acc[kt][2], srcB);
        float y3 = __shfl_sync(0xffffffffu, acc[kt][3], srcB);
        unsigned pa[4];
        pa[0] = cvt_tf32(odd ? x1 : x0);   // P[row g   ][kt*8 + tig]
        pa[1] = cvt_tf32(odd ? x3 : x2);   // P[row g+8 ][kt*8 + tig]
        pa[2] = cvt_tf32(odd ? y1 : y0);   // P[row g   ][kt*8 + tig+4]
        pa[3] = cvt_tf32(odd ? y3 : y2);   // P[row g+8 ][kt*8 + tig+4]
        #pragma unroll
        for (int dt = 0; dt < 4; dt++) {
            unsigned b[2];
            b[0] = __float_as_uint(vs[(kt * 8 + tig) * V_ST + dt * 8 + g]);
            b[1] = __float_as_uint(vs[(kt * 8 + tig + 4) * V_ST + dt * 8 + g]);
            mma_tf32(oacc[dt], pa, b);
        }
    }

    // ---- store: rows i0+g and i0+8+g, cols dt*8 + tig*2 (+1) ----
    const int row0 = i0 + g;
    const int row1 = i0 + 8 + g;
    if (row0 < TWIN) {
        float* o = out + ((size_t)w * TWIN + row0) * CDIM + (size_t)h * HD;
        #pragma unroll
        for (int dt = 0; dt < 4; dt++)
            *(float2*)&o[dt * 8 + tig * 2] = make_float2(oacc[dt][0], oacc[dt][1]);
    }
    if (row1 < TWIN) {
        float* o = out + ((size_t)w * TWIN + row1) * CDIM + (size_t)h * HD;
        #pragma unroll
        for (int dt = 0; dt < 4; dt++)
            *(float2*)&o[dt * 8 + tig * 2] = make_float2(oacc[dt][2], oacc[dt][3]);
    }
}

// ================= launch =================
extern "C" void kernel_launch(void* const* d_in, const int* in_sizes, int n_in,
                              void* d_out, int out_size) {
    const float* x  = (const float*)d_in[0];
    const float* Wq = (const float*)d_in[1];
    const float* bq = (const float*)d_in[2];
    const float* Wk = (const float*)d_in[3];
    const float* bk = (const float*)d_in[4];
    const float* Wv = (const float*)d_in[5];
    const float* bv = (const float*)d_in[6];
    float* out = (float*)d_out;

    cudaFuncSetAttribute(qkv_proj_kernel,
                         cudaFuncAttributeMaxDynamicSharedMemorySize, SMEM_PROJ_BYTES);

    qkv_proj_kernel<<<M_TOK / BM, 256, SMEM_PROJ_BYTES>>>(x, Wq, bq, Wk, bk, Wv, bv);

    dim3 g2(NWIN, NHEADS);                  // 2048 x 8
    attn_kernel<<<g2, 128>>>(out);
}

// round 7
// speedup vs baseline: 2.2512x; 1.0532x over previous
#include <cuda_runtime.h>
#include <cstdint>

// ---------------- problem constants ----------------
#define M_TOK   100352          // 32 * 64 * 49 tokens (window-gathered order)
#define CDIM    256
#define NHEADS  8
#define HD      32
#define TWIN    49
#define NWIN    2048

// scratch
__device__ float g_qkv[3ull * M_TOK * CDIM];   // Q|K|V, window-gathered rows
__device__ float g_x[(size_t)M_TOK * CDIM];    // gathered + tf32-rounded x
__device__ float g_w[768 * CDIM];              // tf32-rounded Wq|Wk|Wv

// ======================= helpers =======================
__device__ __forceinline__ uint32_t smem_u32(const void* p) {
    uint32_t a;
    asm("{ .reg .u64 t; cvta.to.shared.u64 t, %1; cvt.u32.u64 %0, t; }" : "=r"(a) : "l"(p));
    return a;
}
__device__ __forceinline__ unsigned cvt_tf32(float x) {
    unsigned r; asm("cvt.rna.tf32.f32 %0, %1;" : "=r"(r) : "f"(x)); return r;
}
__device__ __forceinline__ float4 cvt4_tf32(float4 v) {
    float4 r;
    r.x = __uint_as_float(cvt_tf32(v.x));
    r.y = __uint_as_float(cvt_tf32(v.y));
    r.z = __uint_as_float(cvt_tf32(v.z));
    r.w = __uint_as_float(cvt_tf32(v.w));
    return r;
}
__device__ __forceinline__ void mma_tf32(float c[4], const unsigned a[4], const unsigned b[2]) {
    asm volatile(
        "mma.sync.aligned.m16n8k8.row.col.f32.tf32.tf32.f32 "
        "{%0,%1,%2,%3}, {%4,%5,%6,%7}, {%8,%9}, {%0,%1,%2,%3};"
        : "+f"(c[0]), "+f"(c[1]), "+f"(c[2]), "+f"(c[3])
        : "r"(a[0]), "r"(a[1]), "r"(a[2]), "r"(a[3]), "r"(b[0]), "r"(b[1]));
}

#define CP_ASYNC16(dst, src) \
    asm volatile("cp.async.cg.shared.global [%0], [%1], 16;" :: "r"(dst), "l"(src))
#define CP_COMMIT() asm volatile("cp.async.commit_group;" ::: "memory")
#define CP_WAIT1()  asm volatile("cp.async.wait_group 1;" ::: "memory")
#define CP_WAIT0()  asm volatile("cp.async.wait_group 0;" ::: "memory")

// ================= Kernel 0: gather + tf32 pre-convert =================
// blocks 0..1567: x -> g_x (window-gathered). blocks 1568..1579: W -> g_w.
__global__ void __launch_bounds__(256) pre_cvt(
    const float* __restrict__ x,
    const float* __restrict__ Wq, const float* __restrict__ Wk, const float* __restrict__ Wv)
{
    const int blk = blockIdx.x;
    const int tid = threadIdx.x;
    const int lrow = tid >> 2;          // 0..63
    const int part = (tid & 3) * 64;    // 64 floats per thread

    const float* src;
    float* dst;
    if (blk < 1568) {
        int p  = blk * 64 + lrow;
        int b  = p / 3136;
        int r  = p - b * 3136;
        int w  = r / 49;
        int t  = r - w * 49;
        int wy = w >> 3, wx = w & 7;
        int ty = t / 7,  tx = t - ty * 7;
        src = x + (size_t)((b * 56 + wy * 7 + ty) * 56 + wx * 7 + tx) * CDIM + part;
        dst = g_x + (size_t)p * CDIM + part;
    } else {
        int r  = (blk - 1568) * 64 + lrow;
        int pr = r >> 8, wr = r & 255;
        const float* W = (pr == 0) ? Wq : ((pr == 1) ? Wk : Wv);
        src = W + (size_t)wr * CDIM + part;
        dst = g_w + (size_t)r * CDIM + part;
    }
    #pragma unroll
    for (int j = 0; j < 16; j++)
        *(float4*)(dst + j * 4) = cvt4_tf32(*(const float4*)(src + j * 4));
}

// ================= Kernel 1: QKV projection (HMMA, 128x128 tile) =================
// 4 warps, each computes a 64x64 output tile: LDS/mma = 1.0 -> tensor-pipe bound.
// 3-stage cp.async pipeline over K (8 chunks of 32).
#define ST_STRIDE 36
#define STAGE_FLOATS (2 * 128 * ST_STRIDE)             // A then B: 9216 floats
#define PROJ_SMEM_BYTES (3 * STAGE_FLOATS * 4)         // 110592

__global__ void __launch_bounds__(128) qkv_proj_tc(
    const float* __restrict__ bq, const float* __restrict__ bk, const float* __restrict__ bv)
{
    extern __shared__ __align__(16) float dsm[];

    const int tid  = threadIdx.x;
    const int warp = tid >> 5;
    const int lane = tid & 31;
    const int g    = lane >> 2;
    const int tig  = lane & 3;
    const int wm   = warp >> 1;     // 0..1
    const int wn   = warp & 1;      // 0..1

    const int p_block = blockIdx.y * 128;
    const int nb      = blockIdx.x;         // 0..5
    const int proj    = nb >> 1;
    const int dloc    = (nb & 1) * 128;
    const float* __restrict__ bias = (proj == 0) ? bq : ((proj == 1) ? bk : bv);

    const int lr = tid >> 3;                // 0..15
    const int kc = (tid & 7) * 4;

    const float* Ag = g_x + (size_t)(p_block + lr) * CDIM + kc;
    const float* Bg = g_w + (size_t)(nb * 128 + lr) * CDIM + kc;
    const uint32_t sbase = smem_u32(dsm);

    auto issue_stage = [&](int stage, int chunk) {
        const uint32_t sA = sbase + (uint32_t)(stage * STAGE_FLOATS) * 4;
        const uint32_t sB = sA + 128 * ST_STRIDE * 4;
        const int ko = chunk * 32;
        #pragma unroll
        for (int i = 0; i < 8; i++) {
            const uint32_t ro = (uint32_t)((lr + 16 * i) * ST_STRIDE + kc) * 4;
            CP_ASYNC16(sA + ro, Ag + (size_t)(16 * i) * CDIM + ko);
            CP_ASYNC16(sB + ro, Bg + (size_t)(16 * i) * CDIM + ko);
        }
        CP_COMMIT();
    };

    issue_stage(0, 0);
    issue_stage(1, 1);

    float acc[4][8][4] = {};

    int stage = 0;
    for (int kt = 0; kt < 8; kt++) {
        if (kt < 7) { CP_WAIT1(); } else { CP_WAIT0(); }
        __syncthreads();

        if (kt + 2 < 8) {
            int ns = stage + 2; if (ns >= 3) ns -= 3;
            issue_stage(ns, kt + 2);
        }

        const float* As = dsm + stage * STAGE_FLOATS;
        const float* Bs = As + 128 * ST_STRIDE;

        #pragma unroll
        for (int ks = 0; ks < 4; ks++) {
            const int kk = ks * 8;
            unsigned a[4][4];
            unsigned b[8][2];
            #pragma unroll
            for (int mt = 0; mt < 4; mt++) {
                int row = wm * 64 + mt * 16 + g;
                a[mt][0] = __float_as_uint(As[row * ST_STRIDE + kk + tig]);
                a[mt][1] = __float_as_uint(As[(row + 8) * ST_STRIDE + kk + tig]);
                a[mt][2] = __float_as_uint(As[row * ST_STRIDE + kk + tig + 4]);
                a[mt][3] = __float_as_uint(As[(row + 8) * ST_STRIDE + kk + tig + 4]);
            }
            #pragma unroll
            for (int nt = 0; nt < 8; nt++) {
                int nrow = wn * 64 + nt * 8 + g;
                b[nt][0] = __float_as_uint(Bs[nrow * ST_STRIDE + kk + tig]);
                b[nt][1] = __float_as_uint(Bs[nrow * ST_STRIDE + kk + tig + 4]);
            }
            #pragma unroll
            for (int mt = 0; mt < 4; mt++)
                #pragma unroll
                for (int nt = 0; nt < 8; nt++)
                    mma_tf32(acc[mt][nt], a[mt], b[nt]);
        }

        stage++; if (stage == 3) stage = 0;
    }

    // ---- epilogue: bias add + store window-gathered rows ----
    const size_t proj_off = (size_t)proj * M_TOK * CDIM;
    float bvs[8][2];
    #pragma unroll
    for (int nt = 0; nt < 8; nt++) {
        int d = dloc + wn * 64 + nt * 8 + tig * 2;
        bvs[nt][0] = bias[d];
        bvs[nt][1] = bias[d + 1];
    }
    #pragma unroll
    for (int mt = 0; mt < 4; mt++) {
        int p0 = p_block + wm * 64 + mt * 16 + g;
        float* r0 = g_qkv + proj_off + (size_t)p0 * CDIM;
        float* r1 = r0 + 8 * CDIM;
        #pragma unroll
        for (int nt = 0; nt < 8; nt++) {
            int d = dloc + wn * 64 + nt * 8 + tig * 2;
            *(float2*)(r0 + d) = make_float2(acc[mt][nt][0] + bvs[nt][0], acc[mt][nt][1] + bvs[nt][1]);
            *(float2*)(r1 + d) = make_float2(acc[mt][nt][2] + bvs[nt][0], acc[mt][nt][3] + bvs[nt][1]);
        }
    }
}

// ================= Kernel 2: tensor-core attention (round-5, unchanged) =================
#define QK_ST 36
#define V_ST  40

__global__ void __launch_bounds__(128) attn_kernel(float* __restrict__ out)
{
    __shared__ __align__(16) float qs[64 * QK_ST];
    __shared__ __align__(16) float ks[56 * QK_ST];
    __shared__ __align__(16) float vs[56 * V_ST];

    const int w   = blockIdx.x;
    const int h   = blockIdx.y;
    const int tid = threadIdx.x;

    const size_t base = (size_t)w * TWIN * CDIM + (size_t)h * HD;

    for (int i = tid; i < 15 * QK_ST; i += 128) qs[49 * QK_ST + i] = 0.f;
    for (int i = tid; i < 7 * QK_ST; i += 128)  ks[49 * QK_ST + i] = 0.f;
    for (int i = tid; i < 7 * V_ST; i += 128)   vs[49 * V_ST + i] = 0.f;

    for (int idx = tid; idx < 3 * TWIN * 8; idx += 128) {
        int mat = idx / (TWIN * 8);
        int rem = idx - mat * (TWIN * 8);
        int t   = rem >> 3;
        int c   = (rem & 7) * 4;
        float4 v = *(const float4*)(g_qkv + (size_t)mat * M_TOK * CDIM + base + (size_t)t * CDIM + c);
        v = cvt4_tf32(v);
        float* dst = (mat == 0) ? qs : ((mat == 1) ? ks : vs);
        int st = (mat == 2) ? V_ST : QK_ST;
        dst[t * st + c + 0] = v.x;
        dst[t * st + c + 1] = v.y;
        dst[t * st + c + 2] = v.z;
        dst[t * st + c + 3] = v.w;
    }
    __syncthreads();

    const int warp = tid >> 5;
    const int lane = tid & 31;
    const int g    = lane >> 2;
    const int tig  = lane & 3;
    const int i0   = warp * 16;

    float acc[7][4] = {};
    #pragma unroll
    for (int kt = 0; kt < 4; kt++) {
        const int c0 = kt * 8;
        unsigned a[4];
        a[0] = __float_as_uint(qs[(i0 + g) * QK_ST + c0 + tig]);
        a[1] = __float_as_uint(qs[(i0 + g + 8) * QK_ST + c0 + tig]);
        a[2] = __float_as_uint(qs[(i0 + g) * QK_ST + c0 + tig + 4]);
        a[3] = __float_as_uint(qs[(i0 + g + 8) * QK_ST + c0 + tig + 4]);
        #pragma unroll
        for (int nt = 0; nt < 7; nt++) {
            unsigned b[2];
            b[0] = __float_as_uint(ks[(nt * 8 + g) * QK_ST + c0 + tig]);
            b[1] = __float_as_uint(ks[(nt * 8 + g) * QK_ST + c0 + tig + 4]);
            mma_tf32(acc[nt], a, b);
        }
    }

    #pragma unroll
    for (int nt = 0; nt < 7; nt++) {
        acc[nt][0] *= 0.0625f; acc[nt][1] *= 0.0625f;
        acc[nt][2] *= 0.0625f; acc[nt][3] *= 0.0625f;
    }
    acc[6][1] = -1e30f; acc[6][3] = -1e30f;
    if (tig > 0) { acc[6][0] = -1e30f; acc[6][2] = -1e30f; }

    float m0 = -1e30f, m1 = -1e30f;
    #pragma unroll
    for (int nt = 0; nt < 7; nt++) {
        m0 = fmaxf(m0, fmaxf(acc[nt][0], acc[nt][1]));
        m1 = fmaxf(m1, fmaxf(acc[nt][2], acc[nt][3]));
    }
    m0 = fmaxf(m0, __shfl_xor_sync(0xffffffffu, m0, 1));
    m0 = fmaxf(m0, __shfl_xor_sync(0xffffffffu, m0, 2));
    m1 = fmaxf(m1, __shfl_xor_sync(0xffffffffu, m1, 1));
    m1 = fmaxf(m1, __shfl_xor_sync(0xffffffffu, m1, 2));

    float s0 = 0.f, s1 = 0.f;
    #pragma unroll
    for (int nt = 0; nt < 7; nt++) {
        acc[nt][0] = __expf(acc[nt][0] - m0);
        acc[nt][1] = __expf(acc[nt][1] - m0);
        acc[nt][2] = __expf(acc[nt][2] - m1);
        acc[nt][3] = __expf(acc[nt][3] - m1);
        s0 += acc[nt][0] + acc[nt][1];
        s1 += acc[nt][2] + acc[nt][3];
    }
    s0 += __shfl_xor_sync(0xffffffffu, s0, 1);
    s0 += __shfl_xor_sync(0xffffffffu, s0, 2);
    s1 += __shfl_xor_sync(0xffffffffu, s1, 1);
    s1 += __shfl_xor_sync(0xffffffffu, s1, 2);
    const float inv0 = 1.f / s0, inv1 = 1.f / s1;
    #pragma unroll
    for (int nt = 0; nt < 7; nt++) {
        acc[nt][0] *= inv0; acc[nt][1] *= inv0;
        acc[nt][2] *= inv1; acc[nt][3] *= inv1;
    }

    float oacc[4][4] = {};
    const int srcA = (lane & ~3) | (tig >> 1);
    const int srcB = srcA + 2;
    const bool odd = tig & 1;

    #pragma unroll
    for (int kt = 0; kt < 7; kt++) {
        float x0 = __shfl_sync(0xffffffffu, acc[kt][0], srcA);
        float x1 = __shfl_sync(0xffffffffu, acc[kt][1], srcA);
        float x2 = __shfl_sync(0xffffffffu, acc[kt][2], srcA);
        float x3 = __shfl_sync(0xffffffffu, acc[kt][3], srcA);
        float y0 = __shfl_sync(0xffffffffu, acc[kt][0], srcB);
        float y1 = __shfl_sync(0xffffffffu, acc[kt][1], srcB);
        float y2 = __shfl_sync(0xffffffffu, acc[kt][2], srcB);
        float y3 = __shfl_sync(0xffffffffu, acc[kt][3], srcB);
        unsigned pa[4];
        pa[0] = cvt_tf32(odd ? x1 : x0);
        pa[1] = cvt_tf32(odd ? x3 : x2);
        pa[2] = cvt_tf32(odd ? y1 : y0);
        pa[3] = cvt_tf32(odd ? y3 : y2);
        #pragma unroll
        for (int dt = 0; dt < 4; dt++) {
            unsigned b[2];
            b[0] = __float_as_uint(vs[(kt * 8 + tig) * V_ST + dt * 8 + g]);
            b[1] = __float_as_uint(vs[(kt * 8 + tig + 4) * V_ST + dt * 8 + g]);
            mma_tf32(oacc[dt], pa, b);
        }
    }

    const int row0 = i0 + g;
    const int row1 = i0 + 8 + g;
    if (row0 < TWIN) {
        float* o = out + ((size_t)w * TWIN + row0) * CDIM + (size_t)h * HD;
        #pragma unroll
        for (int dt = 0; dt < 4; dt++)
            *(float2*)&o[dt * 8 + tig * 2] = make_float2(oacc[dt][0], oacc[dt][1]);
    }
    if (row1 < TWIN) {
        float* o = out + ((size_t)w * TWIN + row1) * CDIM + (size_t)h * HD;
        #pragma unroll
        for (int dt = 0; dt < 4; dt++)
            *(float2*)&o[dt * 8 + tig * 2] = make_float2(oacc[dt][2], oacc[dt][3]);
    }
}

// ================= launch =================
extern "C" void kernel_launch(void* const* d_in, const int* in_sizes, int n_in,
                              void* d_out, int out_size) {
    const float* x  = (const float*)d_in[0];
    const float* Wq = (const float*)d_in[1];
    const float* bq = (const float*)d_in[2];
    const float* Wk = (const float*)d_in[3];
    const float* bk = (const float*)d_in[4];
    const float* Wv = (const float*)d_in[5];
    const float* bv = (const float*)d_in[6];
    float* out = (float*)d_out;

    cudaFuncSetAttribute(qkv_proj_tc,
                         cudaFuncAttributeMaxDynamicSharedMemorySize, PROJ_SMEM_BYTES);

    pre_cvt<<<1580, 256>>>(x, Wq, Wk, Wv);

    dim3 g1(6, M_TOK / 128);                // N-slices fastest -> L2 reuse of g_x
    qkv_proj_tc<<<g1, 128, PROJ_SMEM_BYTES>>>(bq, bk, bv);

    dim3 g2(NWIN, NHEADS);
    attn_kernel<<<g2, 128>>>(out);
}

// round 8
// speedup vs baseline: 3.1847x; 1.4146x over previous
#include <cuda_runtime.h>
#include <cuda_fp16.h>
#include <cstdint>

// ---------------- problem constants ----------------
#define M_TOK   100352          // 32 * 64 * 49 tokens (window-gathered order)
#define CDIM    256
#define NHEADS  8
#define HD      32
#define TWIN    49
#define NWIN    2048

// scratch
__device__ float  g_qkv[3ull * M_TOK * CDIM];   // Q|K|V, window-gathered rows (f32)
__device__ __half g_xh[(size_t)M_TOK * CDIM];   // gathered x, fp16
__device__ __half g_wh[768 * CDIM];             // Wq|Wk|Wv, fp16

// ======================= helpers =======================
__device__ __forceinline__ uint32_t smem_u32(const void* p) {
    uint32_t a;
    asm("{ .reg .u64 t; cvta.to.shared.u64 t, %1; cvt.u32.u64 %0, t; }" : "=r"(a) : "l"(p));
    return a;
}
__device__ __forceinline__ unsigned cvt_tf32(float x) {
    unsigned r; asm("cvt.rna.tf32.f32 %0, %1;" : "=r"(r) : "f"(x)); return r;
}
__device__ __forceinline__ float4 cvt4_tf32(float4 v) {
    float4 r;
    r.x = __uint_as_float(cvt_tf32(v.x));
    r.y = __uint_as_float(cvt_tf32(v.y));
    r.z = __uint_as_float(cvt_tf32(v.z));
    r.w = __uint_as_float(cvt_tf32(v.w));
    return r;
}
__device__ __forceinline__ void mma_tf32(float c[4], const unsigned a[4], const unsigned b[2]) {
    asm volatile(
        "mma.sync.aligned.m16n8k8.row.col.f32.tf32.tf32.f32 "
        "{%0,%1,%2,%3}, {%4,%5,%6,%7}, {%8,%9}, {%0,%1,%2,%3};"
        : "+f"(c[0]), "+f"(c[1]), "+f"(c[2]), "+f"(c[3])
        : "r"(a[0]), "r"(a[1]), "r"(a[2]), "r"(a[3]), "r"(b[0]), "r"(b[1]));
}
__device__ __forceinline__ void mma_f16(float c[4], const unsigned a[4], const unsigned b[2]) {
    asm volatile(
        "mma.sync.aligned.m16n8k16.row.col.f32.f16.f16.f32 "
        "{%0,%1,%2,%3}, {%4,%5,%6,%7}, {%8,%9}, {%0,%1,%2,%3};"
        : "+f"(c[0]), "+f"(c[1]), "+f"(c[2]), "+f"(c[3])
        : "r"(a[0]), "r"(a[1]), "r"(a[2]), "r"(a[3]), "r"(b[0]), "r"(b[1]));
}

#define CP_ASYNC16(dst, src) \
    asm volatile("cp.async.cg.shared.global [%0], [%1], 16;" :: "r"(dst), "l"(src))
#define CP_COMMIT() asm volatile("cp.async.commit_group;" ::: "memory")
#define CP_WAIT1()  asm volatile("cp.async.wait_group 1;" ::: "memory")
#define CP_WAIT0()  asm volatile("cp.async.wait_group 0;" ::: "memory")

// ================= Kernel 0: gather + fp16 pre-convert (coalesced) =================
// One warp per row: lanes cover the 256-float row contiguously.
// blocks 0..12543: x rows -> g_xh (window-gathered). blocks 12544..12639: W -> g_wh.
__global__ void __launch_bounds__(256) pre_cvt_h(
    const float* __restrict__ x,
    const float* __restrict__ Wq, const float* __restrict__ Wk, const float* __restrict__ Wv)
{
    const int blk  = blockIdx.x;
    const int rloc = threadIdx.x >> 5;   // 0..7 rows per block
    const int lane = threadIdx.x & 31;   // 8 halves per lane

    const float* src;
    __half* dst;
    if (blk < 12544) {
        int p  = blk * 8 + rloc;
        int b  = p / 3136;
        int r  = p - b * 3136;
        int w  = r / 49;
        int t  = r - w * 49;
        int wy = w >> 3, wx = w & 7;
        int ty = t / 7,  tx = t - ty * 7;
        src = x + (size_t)((b * 56 + wy * 7 + ty) * 56 + wx * 7 + tx) * CDIM + lane * 8;
        dst = g_xh + (size_t)p * CDIM + lane * 8;
    } else {
        int r  = (blk - 12544) * 8 + rloc;
        int pr = r >> 8, wr = r & 255;
        const float* W = (pr == 0) ? Wq : ((pr == 1) ? Wk : Wv);
        src = W + (size_t)wr * CDIM + lane * 8;
        dst = g_wh + (size_t)r * CDIM + lane * 8;
    }
    float4 v0 = *(const float4*)(src);
    float4 v1 = *(const float4*)(src + 4);
    __half2 o[4];
    o[0] = __float22half2_rn(make_float2(v0.x, v0.y));
    o[1] = __float22half2_rn(make_float2(v0.z, v0.w));
    o[2] = __float22half2_rn(make_float2(v1.x, v1.y));
    o[3] = __float22half2_rn(make_float2(v1.z, v1.w));
    *(uint4*)dst = *(uint4*)o;
}

// ================= Kernel 1: QKV projection (fp16 HMMA, 128x128 tile) =================
// 4 warps, each a 64x64 output tile via m16n8k16. 3-stage cp.async pipeline,
// k-chunk = 32 halves (2 mma k-steps per chunk).
#define HST 40                                   // halves per tile row (64B data + 16B pad)
#define STAGE_HALVES (2 * 128 * HST)             // A then B: 10240 halves = 20480 B
#define PROJ_SMEM_BYTES (3 * STAGE_HALVES * 2)   // 61440

__global__ void __launch_bounds__(128) qkv_proj_fp16(
    const float* __restrict__ bq, const float* __restrict__ bk, const float* __restrict__ bv)
{
    extern __shared__ __align__(16) __half hsm[];

    const int tid  = threadIdx.x;
    const int warp = tid >> 5;
    const int lane = tid & 31;
    const int g    = lane >> 2;
    const int tig  = lane & 3;
    const int wm   = warp >> 1;     // 0..1
    const int wn   = warp & 1;      // 0..1

    const int p_block = blockIdx.y * 128;
    const int nb      = blockIdx.x;         // 0..5
    const int proj    = nb >> 1;
    const int dloc    = (nb & 1) * 128;
    const float* __restrict__ bias = (proj == 0) ? bq : ((proj == 1) ? bk : bv);

    // loader: thread -> (row = tid>>2 + 32i, seg = tid&3), seg = 8 halves (16B)
    const int lrow = tid >> 2;               // 0..31
    const int seg  = tid & 3;
    const __half* Ag = g_xh + (size_t)(p_block + lrow) * CDIM + seg * 8;
    const __half* Bg = g_wh + (size_t)(nb * 128 + lrow) * CDIM + seg * 8;
    const uint32_t sbase = smem_u32(hsm);

    auto issue_stage = [&](int stage, int chunk) {
        const uint32_t sA = sbase + (uint32_t)(stage * STAGE_HALVES) * 2;
        const uint32_t sB = sA + 128 * HST * 2;
        const int ko = chunk * 32;
        #pragma unroll
        for (int i = 0; i < 4; i++) {
            const uint32_t ro = (uint32_t)((lrow + 32 * i) * HST + seg * 8) * 2;
            CP_ASYNC16(sA + ro, Ag + (size_t)(32 * i) * CDIM + ko);
            CP_ASYNC16(sB + ro, Bg + (size_t)(32 * i) * CDIM + ko);
        }
        CP_COMMIT();
    };

    issue_stage(0, 0);
    issue_stage(1, 1);

    float acc[4][8][4] = {};

    int stage = 0;
    for (int kt = 0; kt < 8; kt++) {
        if (kt < 7) { CP_WAIT1(); } else { CP_WAIT0(); }
        __syncthreads();

        if (kt + 2 < 8) {
            int ns = stage + 2; if (ns >= 3) ns -= 3;
            issue_stage(ns, kt + 2);
        }

        const uint32_t* As32 = (const uint32_t*)(hsm + stage * STAGE_HALVES);
        const uint32_t* Bs32 = As32 + 128 * (HST / 2);

        #pragma unroll
        for (int ks = 0; ks < 2; ks++) {
            const int ko = ks * 8;   // word offset within the 20-word row
            unsigned a[4][4];
            unsigned b[8][2];
            #pragma unroll
            for (int mt = 0; mt < 4; mt++) {
                int row = wm * 64 + mt * 16 + g;
                a[mt][0] = As32[row * 20 + ko + tig];
                a[mt][1] = As32[(row + 8) * 20 + ko + tig];
                a[mt][2] = As32[row * 20 + ko + 4 + tig];
                a[mt][3] = As32[(row + 8) * 20 + ko + 4 + tig];
            }
            #pragma unroll
            for (int nt = 0; nt < 8; nt++) {
                int nrow = wn * 64 + nt * 8 + g;
                b[nt][0] = Bs32[nrow * 20 + ko + tig];
                b[nt][1] = Bs32[nrow * 20 + ko + 4 + tig];
            }
            #pragma unroll
            for (int mt = 0; mt < 4; mt++)
                #pragma unroll
                for (int nt = 0; nt < 8; nt++)
                    mma_f16(acc[mt][nt], a[mt], b[nt]);
        }

        stage++; if (stage == 3) stage = 0;
    }

    // ---- epilogue: bias add + store f32 ----
    const size_t proj_off = (size_t)proj * M_TOK * CDIM;
    float bvs[8][2];
    #pragma unroll
    for (int nt = 0; nt < 8; nt++) {
        int d = dloc + wn * 64 + nt * 8 + tig * 2;
        bvs[nt][0] = bias[d];
        bvs[nt][1] = bias[d + 1];
    }
    #pragma unroll
    for (int mt = 0; mt < 4; mt++) {
        int p0 = p_block + wm * 64 + mt * 16 + g;
        float* r0 = g_qkv + proj_off + (size_t)p0 * CDIM;
        float* r1 = r0 + 8 * CDIM;
        #pragma unroll
        for (int nt = 0; nt < 8; nt++) {
            int d = dloc + wn * 64 + nt * 8 + tig * 2;
            *(float2*)(r0 + d) = make_float2(acc[mt][nt][0] + bvs[nt][0], acc[mt][nt][1] + bvs[nt][1]);
            *(float2*)(r1 + d) = make_float2(acc[mt][nt][2] + bvs[nt][0], acc[mt][nt][3] + bvs[nt][1]);
        }
    }
}

// ================= Kernel 2: tensor-core attention (round-5, unchanged) =================
#define QK_ST 36
#define V_ST  40

__global__ void __launch_bounds__(128) attn_kernel(float* __restrict__ out)
{
    __shared__ __align__(16) float qs[64 * QK_ST];
    __shared__ __align__(16) float ks[56 * QK_ST];
    __shared__ __align__(16) float vs[56 * V_ST];

    const int w   = blockIdx.x;
    const int h   = blockIdx.y;
    const int tid = threadIdx.x;

    const size_t base = (size_t)w * TWIN * CDIM + (size_t)h * HD;

    for (int i = tid; i < 15 * QK_ST; i += 128) qs[49 * QK_ST + i] = 0.f;
    for (int i = tid; i < 7 * QK_ST; i += 128)  ks[49 * QK_ST + i] = 0.f;
    for (int i = tid; i < 7 * V_ST; i += 128)   vs[49 * V_ST + i] = 0.f;

    for (int idx = tid; idx < 3 * TWIN * 8; idx += 128) {
        int mat = idx / (TWIN * 8);
        int rem = idx - mat * (TWIN * 8);
        int t   = rem >> 3;
        int c   = (rem & 7) * 4;
        float4 v = *(const float4*)(g_qkv + (size_t)mat * M_TOK * CDIM + base + (size_t)t * CDIM + c);
        v = cvt4_tf32(v);
        float* dst = (mat == 0) ? qs : ((mat == 1) ? ks : vs);
        int st = (mat == 2) ? V_ST : QK_ST;
        dst[t * st + c + 0] = v.x;
        dst[t * st + c + 1] = v.y;
        dst[t * st + c + 2] = v.z;
        dst[t * st + c + 3] = v.w;
    }
    __syncthreads();

    const int warp = tid >> 5;
    const int lane = tid & 31;
    const int g    = lane >> 2;
    const int tig  = lane & 3;
    const int i0   = warp * 16;

    float acc[7][4] = {};
    #pragma unroll
    for (int kt = 0; kt < 4; kt++) {
        const int c0 = kt * 8;
        unsigned a[4];
        a[0] = __float_as_uint(qs[(i0 + g) * QK_ST + c0 + tig]);
        a[1] = __float_as_uint(qs[(i0 + g + 8) * QK_ST + c0 + tig]);
        a[2] = __float_as_uint(qs[(i0 + g) * QK_ST + c0 + tig + 4]);
        a[3] = __float_as_uint(qs[(i0 + g + 8) * QK_ST + c0 + tig + 4]);
        #pragma unroll
        for (int nt = 0; nt < 7; nt++) {
            unsigned b[2];
            b[0] = __float_as_uint(ks[(nt * 8 + g) * QK_ST + c0 + tig]);
            b[1] = __float_as_uint(ks[(nt * 8 + g) * QK_ST + c0 + tig + 4]);
            mma_tf32(acc[nt], a, b);
        }
    }

    #pragma unroll
    for (int nt = 0; nt < 7; nt++) {
        acc[nt][0] *= 0.0625f; acc[nt][1] *= 0.0625f;
        acc[nt][2] *= 0.0625f; acc[nt][3] *= 0.0625f;
    }
    acc[6][1] = -1e30f; acc[6][3] = -1e30f;
    if (tig > 0) { acc[6][0] = -1e30f; acc[6][2] = -1e30f; }

    float m0 = -1e30f, m1 = -1e30f;
    #pragma unroll
    for (int nt = 0; nt < 7; nt++) {
        m0 = fmaxf(m0, fmaxf(acc[nt][0], acc[nt][1]));
        m1 = fmaxf(m1, fmaxf(acc[nt][2], acc[nt][3]));
    }
    m0 = fmaxf(m0, __shfl_xor_sync(0xffffffffu, m0, 1));
    m0 = fmaxf(m0, __shfl_xor_sync(0xffffffffu, m0, 2));
    m1 = fmaxf(m1, __shfl_xor_sync(0xffffffffu, m1, 1));
    m1 = fmaxf(m1, __shfl_xor_sync(0xffffffffu, m1, 2));

    float s0 = 0.f, s1 = 0.f;
    #pragma unroll
    for (int nt = 0; nt < 7; nt++) {
        acc[nt][0] = __expf(acc[nt][0] - m0);
        acc[nt][1] = __expf(acc[nt][1] - m0);
        acc[nt][2] = __expf(acc[nt][2] - m1);
        acc[nt][3] = __expf(acc[nt][3] - m1);
        s0 += acc[nt][0] + acc[nt][1];
        s1 += acc[nt][2] + acc[nt][3];
    }
    s0 += __shfl_xor_sync(0xffffffffu, s0, 1);
    s0 += __shfl_xor_sync(0xffffffffu, s0, 2);
    s1 += __shfl_xor_sync(0xffffffffu, s1, 1);
    s1 += __shfl_xor_sync(0xffffffffu, s1, 2);
    const float inv0 = 1.f / s0, inv1 = 1.f / s1;
    #pragma unroll
    for (int nt = 0; nt < 7; nt++) {
        acc[nt][0] *= inv0; acc[nt][1] *= inv0;
        acc[nt][2] *= inv1; acc[nt][3] *= inv1;
    }

    float oacc[4][4] = {};
    const int srcA = (lane & ~3) | (tig >> 1);
    const int srcB = srcA + 2;
    const bool odd = tig & 1;

    #pragma unroll
    for (int kt = 0; kt < 7; kt++) {
        float x0 = __shfl_sync(0xffffffffu, acc[kt][0], srcA);
        float x1 = __shfl_sync(0xffffffffu, acc[kt][1], srcA);
        float x2 = __shfl_sync(0xffffffffu, acc[kt][2], srcA);
        float x3 = __shfl_sync(0xffffffffu, acc[kt][3], srcA);
        float y0 = __shfl_sync(0xffffffffu, acc[kt][0], srcB);
        float y1 = __shfl_sync(0xffffffffu, acc[kt][1], srcB);
        float y2 = __shfl_sync(0xffffffffu, acc[kt][2], srcB);
        float y3 = __shfl_sync(0xffffffffu, acc[kt][3], srcB);
        unsigned pa[4];
        pa[0] = cvt_tf32(odd ? x1 : x0);
        pa[1] = cvt_tf32(odd ? x3 : x2);
        pa[2] = cvt_tf32(odd ? y1 : y0);
        pa[3] = cvt_tf32(odd ? y3 : y2);
        #pragma unroll
        for (int dt = 0; dt < 4; dt++) {
            unsigned b[2];
            b[0] = __float_as_uint(vs[(kt * 8 + tig) * V_ST + dt * 8 + g]);
            b[1] = __float_as_uint(vs[(kt * 8 + tig + 4) * V_ST + dt * 8 + g]);
            mma_tf32(oacc[dt], pa, b);
        }
    }

    const int row0 = i0 + g;
    const int row1 = i0 + 8 + g;
    if (row0 < TWIN) {
        float* o = out + ((size_t)w * TWIN + row0) * CDIM + (size_t)h * HD;
        #pragma unroll
        for (int dt = 0; dt < 4; dt++)
            *(float2*)&o[dt * 8 + tig * 2] = make_float2(oacc[dt][0], oacc[dt][1]);
    }
    if (row1 < TWIN) {
        float* o = out + ((size_t)w * TWIN + row1) * CDIM + (size_t)h * HD;
        #pragma unroll
        for (int dt = 0; dt < 4; dt++)
            *(float2*)&o[dt * 8 + tig * 2] = make_float2(oacc[dt][2], oacc[dt][3]);
    }
}

// ================= launch =================
extern "C" void kernel_launch(void* const* d_in, const int* in_sizes, int n_in,
                              void* d_out, int out_size) {
    const float* x  = (const float*)d_in[0];
    const float* Wq = (const float*)d_in[1];
    const float* bq = (const float*)d_in[2];
    const float* Wk = (const float*)d_in[3];
    const float* bk = (const float*)d_in[4];
    const float* Wv = (const float*)d_in[5];
    const float* bv = (const float*)d_in[6];
    float* out = (float*)d_out;

    cudaFuncSetAttribute(qkv_proj_fp16,
                         cudaFuncAttributeMaxDynamicSharedMemorySize, PROJ_SMEM_BYTES);

    pre_cvt_h<<<12640, 256>>>(x, Wq, Wk, Wv);

    dim3 g1(6, M_TOK / 128);                // N-slices fastest -> L2 reuse of g_xh
    qkv_proj_fp16<<<g1, 128, PROJ_SMEM_BYTES>>>(bq, bk, bv);

    dim3 g2(NWIN, NHEADS);
    attn_kernel<<<g2, 128>>>(out);
}

// round 9
// speedup vs baseline: 4.0992x; 1.2872x over previous
#include <cuda_runtime.h>
#include <cuda_fp16.h>
#include <cstdint>

// ---------------- problem constants ----------------
#define M_TOK   100352          // 32 * 64 * 49 tokens (window-gathered order)
#define CDIM    256
#define NHEADS  8
#define HD      32
#define TWIN    49
#define NWIN    2048

// scratch (all fp16 intermediates)
__device__ __half g_qkvh[3ull * M_TOK * CDIM];  // Q|K|V, window-gathered rows
__device__ __half g_xh[(size_t)M_TOK * CDIM];   // gathered x
__device__ __half g_wh[768 * CDIM];             // Wq|Wk|Wv

// ======================= helpers =======================
__device__ __forceinline__ uint32_t smem_u32(const void* p) {
    uint32_t a;
    asm("{ .reg .u64 t; cvta.to.shared.u64 t, %1; cvt.u32.u64 %0, t; }" : "=r"(a) : "l"(p));
    return a;
}
__device__ __forceinline__ void mma_f16(float c[4], const unsigned a[4], const unsigned b[2]) {
    asm volatile(
        "mma.sync.aligned.m16n8k16.row.col.f32.f16.f16.f32 "
        "{%0,%1,%2,%3}, {%4,%5,%6,%7}, {%8,%9}, {%0,%1,%2,%3};"
        : "+f"(c[0]), "+f"(c[1]), "+f"(c[2]), "+f"(c[3])
        : "r"(a[0]), "r"(a[1]), "r"(a[2]), "r"(a[3]), "r"(b[0]), "r"(b[1]));
}
__device__ __forceinline__ unsigned pack_h2(float lo, float hi) {
    __half2 h = __float22half2_rn(make_float2(lo, hi));
    return *(unsigned*)&h;
}

#define CP_ASYNC16(dst, src) \
    asm volatile("cp.async.cg.shared.global [%0], [%1], 16;" :: "r"(dst), "l"(src))
#define CP_COMMIT() asm volatile("cp.async.commit_group;" ::: "memory")
#define CP_WAIT1()  asm volatile("cp.async.wait_group 1;" ::: "memory")
#define CP_WAIT0()  asm volatile("cp.async.wait_group 0;" ::: "memory")

// ================= Kernel 0: gather + fp16 pre-convert (coalesced) =================
__global__ void __launch_bounds__(256) pre_cvt_h(
    const float* __restrict__ x,
    const float* __restrict__ Wq, const float* __restrict__ Wk, const float* __restrict__ Wv)
{
    const int blk  = blockIdx.x;
    const int rloc = threadIdx.x >> 5;
    const int lane = threadIdx.x & 31;

    const float* src;
    __half* dst;
    if (blk < 12544) {
        int p  = blk * 8 + rloc;
        int b  = p / 3136;
        int r  = p - b * 3136;
        int w  = r / 49;
        int t  = r - w * 49;
        int wy = w >> 3, wx = w & 7;
        int ty = t / 7,  tx = t - ty * 7;
        src = x + (size_t)((b * 56 + wy * 7 + ty) * 56 + wx * 7 + tx) * CDIM + lane * 8;
        dst = g_xh + (size_t)p * CDIM + lane * 8;
    } else {
        int r  = (blk - 12544) * 8 + rloc;
        int pr = r >> 8, wr = r & 255;
        const float* W = (pr == 0) ? Wq : ((pr == 1) ? Wk : Wv);
        src = W + (size_t)wr * CDIM + lane * 8;
        dst = g_wh + (size_t)r * CDIM + lane * 8;
    }
    float4 v0 = *(const float4*)(src);
    float4 v1 = *(const float4*)(src + 4);
    __half2 o[4];
    o[0] = __float22half2_rn(make_float2(v0.x, v0.y));
    o[1] = __float22half2_rn(make_float2(v0.z, v0.w));
    o[2] = __float22half2_rn(make_float2(v1.x, v1.y));
    o[3] = __float22half2_rn(make_float2(v1.z, v1.w));
    *(uint4*)dst = *(uint4*)o;
}

// ================= Kernel 1: QKV projection (fp16 HMMA, 128x128 tile) =================
#define HST 40
#define STAGE_HALVES (2 * 128 * HST)
#define PROJ_SMEM_BYTES (3 * STAGE_HALVES * 2)   // 61440

__global__ void __launch_bounds__(128) qkv_proj_fp16(
    const float* __restrict__ bq, const float* __restrict__ bk, const float* __restrict__ bv)
{
    extern __shared__ __align__(16) __half hsm[];

    const int tid  = threadIdx.x;
    const int warp = tid >> 5;
    const int lane = tid & 31;
    const int g    = lane >> 2;
    const int tig  = lane & 3;
    const int wm   = warp >> 1;
    const int wn   = warp & 1;

    const int p_block = blockIdx.y * 128;
    const int nb      = blockIdx.x;
    const int proj    = nb >> 1;
    const int dloc    = (nb & 1) * 128;
    const float* __restrict__ bias = (proj == 0) ? bq : ((proj == 1) ? bk : bv);

    const int lrow = tid >> 2;
    const int seg  = tid & 3;
    const __half* Ag = g_xh + (size_t)(p_block + lrow) * CDIM + seg * 8;
    const __half* Bg = g_wh + (size_t)(nb * 128 + lrow) * CDIM + seg * 8;
    const uint32_t sbase = smem_u32(hsm);

    auto issue_stage = [&](int stage, int chunk) {
        const uint32_t sA = sbase + (uint32_t)(stage * STAGE_HALVES) * 2;
        const uint32_t sB = sA + 128 * HST * 2;
        const int ko = chunk * 32;
        #pragma unroll
        for (int i = 0; i < 4; i++) {
            const uint32_t ro = (uint32_t)((lrow + 32 * i) * HST + seg * 8) * 2;
            CP_ASYNC16(sA + ro, Ag + (size_t)(32 * i) * CDIM + ko);
            CP_ASYNC16(sB + ro, Bg + (size_t)(32 * i) * CDIM + ko);
        }
        CP_COMMIT();
    };

    issue_stage(0, 0);
    issue_stage(1, 1);

    float acc[4][8][4] = {};

    int stage = 0;
    for (int kt = 0; kt < 8; kt++) {
        if (kt < 7) { CP_WAIT1(); } else { CP_WAIT0(); }
        __syncthreads();

        if (kt + 2 < 8) {
            int ns = stage + 2; if (ns >= 3) ns -= 3;
            issue_stage(ns, kt + 2);
        }

        const uint32_t* As32 = (const uint32_t*)(hsm + stage * STAGE_HALVES);
        const uint32_t* Bs32 = As32 + 128 * (HST / 2);

        #pragma unroll
        for (int ks = 0; ks < 2; ks++) {
            const int ko = ks * 8;
            unsigned a[4][4];
            unsigned b[8][2];
            #pragma unroll
            for (int mt = 0; mt < 4; mt++) {
                int row = wm * 64 + mt * 16 + g;
                a[mt][0] = As32[row * 20 + ko + tig];
                a[mt][1] = As32[(row + 8) * 20 + ko + tig];
                a[mt][2] = As32[row * 20 + ko + 4 + tig];
                a[mt][3] = As32[(row + 8) * 20 + ko + 4 + tig];
            }
            #pragma unroll
            for (int nt = 0; nt < 8; nt++) {
                int nrow = wn * 64 + nt * 8 + g;
                b[nt][0] = Bs32[nrow * 20 + ko + tig];
                b[nt][1] = Bs32[nrow * 20 + ko + 4 + tig];
            }
            #pragma unroll
            for (int mt = 0; mt < 4; mt++)
                #pragma unroll
                for (int nt = 0; nt < 8; nt++)
                    mma_f16(acc[mt][nt], a[mt], b[nt]);
        }

        stage++; if (stage == 3) stage = 0;
    }

    // ---- epilogue: bias add + fp16 store ----
    const size_t proj_off = (size_t)proj * M_TOK * CDIM;
    float bvs[8][2];
    #pragma unroll
    for (int nt = 0; nt < 8; nt++) {
        int d = dloc + wn * 64 + nt * 8 + tig * 2;
        bvs[nt][0] = bias[d];
        bvs[nt][1] = bias[d + 1];
    }
    #pragma unroll
    for (int mt = 0; mt < 4; mt++) {
        int p0 = p_block + wm * 64 + mt * 16 + g;
        __half* r0 = g_qkvh + proj_off + (size_t)p0 * CDIM;
        __half* r1 = r0 + 8 * CDIM;
        #pragma unroll
        for (int nt = 0; nt < 8; nt++) {
            int d = dloc + wn * 64 + nt * 8 + tig * 2;
            *(unsigned*)(r0 + d) = pack_h2(acc[mt][nt][0] + bvs[nt][0], acc[mt][nt][1] + bvs[nt][1]);
            *(unsigned*)(r1 + d) = pack_h2(acc[mt][nt][2] + bvs[nt][0], acc[mt][nt][3] + bvs[nt][1]);
        }
    }
}

// ================= Kernel 2: fp16 tensor-core attention =================
// qs/ks: [rows][40 halves]; vt: V transposed [d=32][72 halves] (j contiguous).
// QK^T C-frag == PV A-frag after half2 packing -> no shuffles.
#define QH_ST 40
#define VT_ST 72

__global__ void __launch_bounds__(128) attn_kernel(float* __restrict__ out)
{
    __shared__ __align__(16) __half qs[64 * QH_ST];
    __shared__ __align__(16) __half ks[56 * QH_ST];
    __shared__ __align__(16) __half vt[32 * VT_ST];

    const int w   = blockIdx.x;
    const int h   = blockIdx.y;
    const int tid = threadIdx.x;

    const size_t base = (size_t)w * TWIN * CDIM + (size_t)h * HD;

    // zero pads: qs rows 49..63, ks rows 49..55, vt cols 49..64 (all rows)
    for (int i = tid; i < 15 * QH_ST; i += 128) qs[49 * QH_ST + i] = __half(0.f);
    for (int i = tid; i < 7 * QH_ST; i += 128)  ks[49 * QH_ST + i] = __half(0.f);
    for (int i = tid; i < 32 * 16; i += 128) {
        int d = i >> 4, c = 49 + (i & 15);
        vt[d * VT_ST + c] = __half(0.f);
    }

    // load q,k: [49 x 32] halves, direct uint4 copies
    for (int idx = tid; idx < 2 * TWIN * 4; idx += 128) {
        int mat = idx / (TWIN * 4);
        int rem = idx - mat * (TWIN * 4);
        int t   = rem >> 2;
        int seg = rem & 3;
        uint4 v = *(const uint4*)(g_qkvh + (size_t)mat * M_TOK * CDIM + base + (size_t)t * CDIM + seg * 8);
        __half* dst = (mat == 0) ? qs : ks;
        *(uint4*)&dst[t * QH_ST + seg * 8] = v;
    }
    // load v transposed: vt[c][t] = V[t][c]
    for (int idx = tid; idx < TWIN * 4; idx += 128) {
        int t   = idx >> 2;
        int seg = idx & 3;
        uint4 raw = *(const uint4*)(g_qkvh + (size_t)2 * M_TOK * CDIM + base + (size_t)t * CDIM + seg * 8);
        __half hv[8];
        *(uint4*)hv = raw;
        #pragma unroll
        for (int i = 0; i < 8; i++)
            vt[(seg * 8 + i) * VT_ST + t] = hv[i];
    }
    __syncthreads();

    const int warp = tid >> 5;
    const int lane = tid & 31;
    const int g    = lane >> 2;
    const int tig  = lane & 3;
    const int i0   = warp * 16;

    const uint32_t* qw = (const uint32_t*)qs;   // word stride 20
    const uint32_t* kw = (const uint32_t*)ks;
    const uint32_t* vw = (const uint32_t*)vt;   // word stride 36

    // ---- QK^T: 2 k16-steps x 7 key-tiles ----
    float acc[7][4] = {};
    #pragma unroll
    for (int ks16 = 0; ks16 < 2; ks16++) {
        const int c0 = ks16 * 8;    // word offset
        unsigned a[4];
        a[0] = qw[(i0 + g) * 20 + c0 + tig];
        a[1] = qw[(i0 + g + 8) * 20 + c0 + tig];
        a[2] = qw[(i0 + g) * 20 + c0 + 4 + tig];
        a[3] = qw[(i0 + g + 8) * 20 + c0 + 4 + tig];
        #pragma unroll
        for (int nt = 0; nt < 7; nt++) {
            unsigned b[2];
            b[0] = kw[(nt * 8 + g) * 20 + c0 + tig];
            b[1] = kw[(nt * 8 + g) * 20 + c0 + 4 + tig];
            mma_f16(acc[nt], a, b);
        }
    }

    // ---- scale + mask padded key cols (j >= 49; tile 6 covers 48..55) ----
    #pragma unroll
    for (int nt = 0; nt < 7; nt++) {
        acc[nt][0] *= 0.0625f; acc[nt][1] *= 0.0625f;
        acc[nt][2] *= 0.0625f; acc[nt][3] *= 0.0625f;
    }
    acc[6][1] = -1e30f; acc[6][3] = -1e30f;          // odd cols: j = 49 + 2tig
    if (tig > 0) { acc[6][0] = -1e30f; acc[6][2] = -1e30f; }   // even: j = 48 + 2tig

    // ---- softmax on fragments ----
    float m0 = -1e30f, m1 = -1e30f;
    #pragma unroll
    for (int nt = 0; nt < 7; nt++) {
        m0 = fmaxf(m0, fmaxf(acc[nt][0], acc[nt][1]));
        m1 = fmaxf(m1, fmaxf(acc[nt][2], acc[nt][3]));
    }
    m0 = fmaxf(m0, __shfl_xor_sync(0xffffffffu, m0, 1));
    m0 = fmaxf(m0, __shfl_xor_sync(0xffffffffu, m0, 2));
    m1 = fmaxf(m1, __shfl_xor_sync(0xffffffffu, m1, 1));
    m1 = fmaxf(m1, __shfl_xor_sync(0xffffffffu, m1, 2));

    float s0 = 0.f, s1 = 0.f;
    #pragma unroll
    for (int nt = 0; nt < 7; nt++) {
        acc[nt][0] = __expf(acc[nt][0] - m0);
        acc[nt][1] = __expf(acc[nt][1] - m0);
        acc[nt][2] = __expf(acc[nt][2] - m1);
        acc[nt][3] = __expf(acc[nt][3] - m1);
        s0 += acc[nt][0] + acc[nt][1];
        s1 += acc[nt][2] + acc[nt][3];
    }
    s0 += __shfl_xor_sync(0xffffffffu, s0, 1);
    s0 += __shfl_xor_sync(0xffffffffu, s0, 2);
    s1 += __shfl_xor_sync(0xffffffffu, s1, 1);
    s1 += __shfl_xor_sync(0xffffffffu, s1, 2);
    const float inv0 = 1.f / s0, inv1 = 1.f / s1;
    #pragma unroll
    for (int nt = 0; nt < 7; nt++) {
        acc[nt][0] *= inv0; acc[nt][1] *= inv0;
        acc[nt][2] *= inv1; acc[nt][3] *= inv1;
    }

    // ---- PV: C-frag == A-frag (pack to half2), 4 k16-tiles x 4 d-tiles ----
    float oacc[4][4] = {};
    #pragma unroll
    for (int t = 0; t < 4; t++) {
        const int n0 = 2 * t, n1 = 2 * t + 1;
        unsigned pa[4];
        pa[0] = pack_h2(acc[n0][0], acc[n0][1]);
        pa[1] = pack_h2(acc[n0][2], acc[n0][3]);
        pa[2] = (n1 < 7) ? pack_h2(acc[n1][0], acc[n1][1]) : 0u;
        pa[3] = (n1 < 7) ? pack_h2(acc[n1][2], acc[n1][3]) : 0u;
        #pragma unroll
        for (int dt = 0; dt < 4; dt++) {
            unsigned b[2];
            b[0] = vw[(dt * 8 + g) * 36 + 8 * t + tig];
            b[1] = vw[(dt * 8 + g) * 36 + 8 * t + tig + 4];
            mma_f16(oacc[dt], pa, b);
        }
    }

    // ---- store: rows i0+g / i0+8+g, cols dt*8 + 2tig (+1) ----
    const int row0 = i0 + g;
    const int row1 = i0 + 8 + g;
    if (row0 < TWIN) {
        float* o = out + ((size_t)w * TWIN + row0) * CDIM + (size_t)h * HD;
        #pragma unroll
        for (int dt = 0; dt < 4; dt++)
            *(float2*)&o[dt * 8 + tig * 2] = make_float2(oacc[dt][0], oacc[dt][1]);
    }
    if (row1 < TWIN) {
        float* o = out + ((size_t)w * TWIN + row1) * CDIM + (size_t)h * HD;
        #pragma unroll
        for (int dt = 0; dt < 4; dt++)
            *(float2*)&o[dt * 8 + tig * 2] = make_float2(oacc[dt][2], oacc[dt][3]);
    }
}

// ================= launch =================
extern "C" void kernel_launch(void* const* d_in, const int* in_sizes, int n_in,
                              void* d_out, int out_size) {
    const float* x  = (const float*)d_in[0];
    const float* Wq = (const float*)d_in[1];
    const float* bq = (const float*)d_in[2];
    const float* Wk = (const float*)d_in[3];
    const float* bk = (const float*)d_in[4];
    const float* Wv = (const float*)d_in[5];
    const float* bv = (const float*)d_in[6];
    float* out = (float*)d_out;

    cudaFuncSetAttribute(qkv_proj_fp16,
                         cudaFuncAttributeMaxDynamicSharedMemorySize, PROJ_SMEM_BYTES);

    pre_cvt_h<<<12640, 256>>>(x, Wq, Wk, Wv);

    dim3 g1(6, M_TOK / 128);
    qkv_proj_fp16<<<g1, 128, PROJ_SMEM_BYTES>>>(bq, bk, bv);

    dim3 g2(NWIN, NHEADS);
    attn_kernel<<<g2, 128>>>(out);
}